// round 7
// baseline (speedup 1.0000x reference)
#include <cuda_runtime.h>
#include <cuda_fp16.h>
#include <cstdint>
#include <math.h>

// Fixed shapes: B=8, C=256, H=128, W=128, heads=8, e=32
#define MROWS 131072
#define CDIM  256
#define NELEM (MROWS * CDIM)

// Scratch (allocation-free rule: __device__ globals)
__device__ float g_q[NELEM];
__device__ float g_k[NELEM];
__device__ float g_v[NELEM];
__device__ float g_attn[NELEM];

// ---------------------------------------------------------------------------
// PTX helpers (sm_80-level: ldmatrix + mma.sync only)
// ---------------------------------------------------------------------------
__device__ __forceinline__ uint32_t smem_u32(const void* p) {
    uint32_t a;
    asm("{ .reg .u64 t; cvta.to.shared.u64 t, %1; cvt.u32.u64 %0, t; }"
        : "=r"(a) : "l"(p));
    return a;
}

#define LDSM_X4(r0, r1, r2, r3, addr)                                         \
    asm volatile("ldmatrix.sync.aligned.m8n8.x4.shared.b16 {%0,%1,%2,%3}, [%4];" \
                 : "=r"(r0), "=r"(r1), "=r"(r2), "=r"(r3) : "r"(addr))

#define MMA16816(d, a, b0, b1)                                                \
    asm volatile("mma.sync.aligned.m16n8k16.row.col.f32.f16.f16.f32 "         \
                 "{%0,%1,%2,%3}, {%4,%5,%6,%7}, {%8,%9}, {%0,%1,%2,%3};"      \
                 : "+f"((d)[0]), "+f"((d)[1]), "+f"((d)[2]), "+f"((d)[3])     \
                 : "r"((a)[0]), "r"((a)[1]), "r"((a)[2]), "r"((a)[3]),        \
                   "r"(b0), "r"(b1))

__device__ __forceinline__ uint32_t packh2(float x, float y) {
    __half2 h = __floats2half2_rn(x, y);
    return *(uint32_t*)&h;
}

// Swizzled byte offset for chunk (row, c) of a [rows][32]-fp16 tile
// (pair-rows of 128B; c = 16B chunk index 0..3). Works for rows<=256.
__device__ __forceinline__ uint32_t tile_off(int row, int c) {
    const int pr = row >> 1;
    const int ch = ((row & 1) << 2) | c;
    return (uint32_t)(pr * 128 + ((ch ^ (pr & 7)) << 4));
}

// ---------------------------------------------------------------------------
// Fused projection kernel. Per CTA: 64 rows of the flat (M,256) view.
// Stages x/ctx tiles once (fp16, swizzled, chunk-major), then runs five
// N=256 GEMMs (Wscale, Wshift, Wq, Wk, Wv) streaming 256x32 weight chunks.
// scale/shift stay in smem (fp32); FiLM fused into q/k/v epilogues.
// ---------------------------------------------------------------------------
#define FP_SMEM (229376 + 1024)   // 224KB tiles + align slack

// smem map (from 1024-aligned base):
//  XT  : 0      .. 32KB   x tile, 8 chunks x [64][32] fp16 (4KB each)
//  CT  : 32KB   .. 64KB   ctx tile
//  WB0 : 64KB   .. 80KB   weight chunk buf 0 ([256][32] fp16)
//  WB1 : 80KB   .. 96KB   weight chunk buf 1
//  SC  : 96KB   .. 160KB  scale [64][256] fp32, shifted cols
//  SH  : 160KB  .. 224KB  shift

__global__ void __launch_bounds__(256, 1)
fused_proj(const float* __restrict__ x, const float* __restrict__ ctx,
           const float* __restrict__ Wq, const float* __restrict__ Wkv,
           const float* __restrict__ Wscale, const float* __restrict__ Wshift,
           float* __restrict__ outq, float* __restrict__ outk,
           float* __restrict__ outv)
{
    extern __shared__ uint8_t smraw[];
    const uint32_t base = (smem_u32(smraw) + 1023u) & ~1023u;
    const uint32_t XT  = base;
    const uint32_t CT  = base + 32768;
    const uint32_t WB0 = base + 65536;
    const uint32_t WB1 = base + 81920;
    const uint32_t SC  = base + 98304;
    const uint32_t SH  = base + 163840;

    const int tid = threadIdx.x, wid = tid >> 5, lane = tid & 31;
    const int m0 = blockIdx.x * 64;
    const int warp_m = (wid & 1) * 32;   // 2 warps down M (64)
    const int warp_n = (wid >> 1) * 64;  // 4 warps across N (256)

    // ---- Stage x & ctx tiles: 64 rows x 256 fp32 -> fp16 chunk-major ----
    {
        const float* xp = x   + (size_t)m0 * CDIM;
        const float* cp = ctx + (size_t)m0 * CDIM;
        #pragma unroll
        for (int i = 0; i < 8; i++) {
            const int unit = i * 256 + tid;       // 2048 units of 8 floats
            const int row = unit >> 5, u = unit & 31;
            const int kc = u >> 2, c = u & 3;
            const uint32_t so = (uint32_t)(kc * 4096) + tile_off(row, c);
            const float4* p = (const float4*)(xp + row * CDIM + u * 8);
            float4 f0 = p[0], f1 = p[1];
            uint4 v;
            v.x = packh2(f0.x, f0.y); v.y = packh2(f0.z, f0.w);
            v.z = packh2(f1.x, f1.y); v.w = packh2(f1.z, f1.w);
            asm volatile("st.shared.v4.b32 [%0], {%1,%2,%3,%4};" ::
                "r"(XT + so), "r"(v.x), "r"(v.y), "r"(v.z), "r"(v.w) : "memory");
            p = (const float4*)(cp + row * CDIM + u * 8);
            f0 = p[0]; f1 = p[1];
            v.x = packh2(f0.x, f0.y); v.y = packh2(f0.z, f0.w);
            v.z = packh2(f1.x, f1.y); v.w = packh2(f1.z, f1.w);
            asm volatile("st.shared.v4.b32 [%0], {%1,%2,%3,%4};" ::
                "r"(CT + so), "r"(v.x), "r"(v.y), "r"(v.z), "r"(v.w) : "memory");
        }
    }
    __syncthreads();

    // ---- Weight chunk load helpers ----
    uint4 pw[4];
    auto ldw = [&](const float* Wp, int kt) {
        #pragma unroll
        for (int i = 0; i < 4; i++) {
            const int idx = i * 256 + tid;        // 1024 units (256 rows x 4)
            const int row = idx >> 2, c = idx & 3;
            const float4* p = (const float4*)(Wp + (size_t)row * CDIM + kt * 32 + c * 8);
            const float4 f0 = p[0], f1 = p[1];
            pw[i].x = packh2(f0.x, f0.y); pw[i].y = packh2(f0.z, f0.w);
            pw[i].z = packh2(f1.x, f1.y); pw[i].w = packh2(f1.z, f1.w);
        }
    };
    auto stw = [&](uint32_t buf) {
        #pragma unroll
        for (int i = 0; i < 4; i++) {
            const int idx = i * 256 + tid;
            const int row = idx >> 2, c = idx & 3;
            asm volatile("st.shared.v4.b32 [%0], {%1,%2,%3,%4};" ::
                "r"(buf + tile_off(row, c)),
                "r"(pw[i].x), "r"(pw[i].y), "r"(pw[i].z), "r"(pw[i].w) : "memory");
        }
    };

    float d[2][8][4];
    auto do_gemm = [&](const float* Wp, uint32_t at) {
        #pragma unroll
        for (int mt = 0; mt < 2; mt++)
            #pragma unroll
            for (int nt = 0; nt < 8; nt++)
                #pragma unroll
                for (int i = 0; i < 4; i++) d[mt][nt][i] = 0.f;
        ldw(Wp, 0); stw(WB0);
        __syncthreads();
        #pragma unroll 1
        for (int kt = 0; kt < 8; kt++) {
            if (kt < 7) ldw(Wp, kt + 1);
            const uint32_t wb = (kt & 1) ? WB1 : WB0;
            const uint32_t ac = at + kt * 4096;
            #pragma unroll
            for (int s = 0; s < 2; s++) {
                uint32_t a[2][4];
                #pragma unroll
                for (int mt = 0; mt < 2; mt++) {
                    const int R = warp_m + mt * 16 + (lane & 15);
                    const int c = s * 2 + (lane >> 4);
                    LDSM_X4(a[mt][0], a[mt][1], a[mt][2], a[mt][3],
                            ac + tile_off(R, c));
                }
                #pragma unroll
                for (int np = 0; np < 4; np++) {
                    const int g = lane >> 3, lr = lane & 7;
                    const int Rn = warp_n + np * 16 + ((g >> 1) << 3) + lr;
                    const int c = s * 2 + (g & 1);
                    uint32_t b[4];
                    LDSM_X4(b[0], b[1], b[2], b[3], wb + tile_off(Rn, c));
                    #pragma unroll
                    for (int mt = 0; mt < 2; mt++) {
                        MMA16816(d[mt][np * 2 + 0], a[mt], b[0], b[1]);
                        MMA16816(d[mt][np * 2 + 1], a[mt], b[2], b[3]);
                    }
                }
            }
            __syncthreads();
            if (kt < 7) { stw((kt & 1) ? WB0 : WB1); __syncthreads(); }
        }
    };

    // shifted fp32 [64][256] smem accessors (write/read same-thread)
    auto smoff = [&](int row, int col) -> uint32_t {
        const int colp = (col + row * 8) & 255;
        return (uint32_t)(row * 1024 + colp * 4);
    };

    // ---- scale, shift (from ctx tile) -> smem ----
    const float* Wmats[2] = {Wscale, Wshift};
    const uint32_t Sm[2] = {SC, SH};
    #pragma unroll 1
    for (int mphase = 0; mphase < 2; mphase++) {
        do_gemm(Wmats[mphase], CT);
        #pragma unroll
        for (int mt = 0; mt < 2; mt++)
            #pragma unroll
            for (int half = 0; half < 2; half++) {
                const int row = warp_m + mt * 16 + (lane >> 2) + half * 8;
                #pragma unroll
                for (int nt = 0; nt < 8; nt++) {
                    const int col = warp_n + nt * 8 + (lane & 3) * 2;
                    asm volatile("st.shared.v2.b32 [%0], {%1,%2};" ::
                        "r"(Sm[mphase] + smoff(row, col)),
                        "r"(__float_as_uint(d[mt][nt][half * 2 + 0])),
                        "r"(__float_as_uint(d[mt][nt][half * 2 + 1])) : "memory");
                }
            }
        __syncthreads();
    }

    // ---- q, k, v (from x tile) with fused FiLM ----
    const float* Wqkv[3] = {Wq, Wkv, Wkv + 256 * CDIM};
    float* Outs[3] = {outq, outk, outv};
    #pragma unroll 1
    for (int mphase = 0; mphase < 3; mphase++) {
        do_gemm(Wqkv[mphase], XT);
        float* outp = Outs[mphase];
        #pragma unroll
        for (int mt = 0; mt < 2; mt++)
            #pragma unroll
            for (int half = 0; half < 2; half++) {
                const int row = warp_m + mt * 16 + (lane >> 2) + half * 8;
                const size_t rbase = (size_t)(m0 + row) * CDIM;
                #pragma unroll
                for (int nt = 0; nt < 8; nt++) {
                    const int col = warp_n + nt * 8 + (lane & 3) * 2;
                    uint32_t sx, sy, tx, ty;
                    asm volatile("ld.shared.v2.b32 {%0,%1}, [%2];"
                        : "=r"(sx), "=r"(sy) : "r"(SC + smoff(row, col)));
                    asm volatile("ld.shared.v2.b32 {%0,%1}, [%2];"
                        : "=r"(tx), "=r"(ty) : "r"(SH + smoff(row, col)));
                    float2 v;
                    v.x = fmaf(__uint_as_float(sx), d[mt][nt][half * 2 + 0],
                               __uint_as_float(tx));
                    v.y = fmaf(__uint_as_float(sy), d[mt][nt][half * 2 + 1],
                               __uint_as_float(ty));
                    *(float2*)(outp + rbase + col) = v;
                }
            }
        __syncthreads();
    }
}

// ---------------------------------------------------------------------------
// Plain fp16 tensor-core GEMM (out-projection): out = A @ W^T, K=256.
// ---------------------------------------------------------------------------
__global__ void __launch_bounds__(256)
gemm_h16(const float* __restrict__ A, const float* __restrict__ W,
         float* __restrict__ out)
{
    constexpr int K = 256;
    __shared__ alignas(128) uint8_t sA[2][8192];
    __shared__ alignas(128) uint8_t sB[2][8192];

    const int tid  = threadIdx.x;
    const int wid  = tid >> 5;
    const int lane = tid & 31;
    const int m0 = blockIdx.y * 128;
    const int n0 = blockIdx.x * 128;

    const int warp_m = (wid & 3) * 32;
    const int warp_n = (wid >> 2) * 64;

    const uint32_t sa0 = smem_u32(&sA[0][0]);
    const uint32_t sa1 = smem_u32(&sA[1][0]);
    const uint32_t sb0 = smem_u32(&sB[0][0]);
    const uint32_t sb1 = smem_u32(&sB[1][0]);

    const int r0i = tid >> 2, c0i = tid & 3;
    const int r1i = (tid + 256) >> 2, c1i = tid & 3;
    const float* Ap = A + (size_t)m0 * K;
    const float* Wp = W + (size_t)n0 * K;

    float d[2][8][4];
    #pragma unroll
    for (int mt = 0; mt < 2; mt++)
        #pragma unroll
        for (int nt = 0; nt < 8; nt++)
            #pragma unroll
            for (int i = 0; i < 4; i++) d[mt][nt][i] = 0.f;

    uint4 pa[2], pb[2];
    auto ldcvt = [&](const float* base, int row, int c, int kt) -> uint4 {
        const float4* p = (const float4*)(base + (size_t)row * K + kt * 32 + c * 8);
        const float4 f0 = p[0], f1 = p[1];
        uint4 u;
        u.x = packh2(f0.x, f0.y); u.y = packh2(f0.z, f0.w);
        u.z = packh2(f1.x, f1.y); u.w = packh2(f1.z, f1.w);
        return u;
    };
    auto store_stage = [&](uint32_t abuf, uint32_t bbuf) {
        asm volatile("st.shared.v4.b32 [%0], {%1,%2,%3,%4};" ::
            "r"(abuf + tile_off(r0i, c0i)), "r"(pa[0].x), "r"(pa[0].y), "r"(pa[0].z), "r"(pa[0].w) : "memory");
        asm volatile("st.shared.v4.b32 [%0], {%1,%2,%3,%4};" ::
            "r"(abuf + tile_off(r1i, c1i)), "r"(pa[1].x), "r"(pa[1].y), "r"(pa[1].z), "r"(pa[1].w) : "memory");
        asm volatile("st.shared.v4.b32 [%0], {%1,%2,%3,%4};" ::
            "r"(bbuf + tile_off(r0i, c0i)), "r"(pb[0].x), "r"(pb[0].y), "r"(pb[0].z), "r"(pb[0].w) : "memory");
        asm volatile("st.shared.v4.b32 [%0], {%1,%2,%3,%4};" ::
            "r"(bbuf + tile_off(r1i, c1i)), "r"(pb[1].x), "r"(pb[1].y), "r"(pb[1].z), "r"(pb[1].w) : "memory");
    };

    pa[0] = ldcvt(Ap, r0i, c0i, 0); pa[1] = ldcvt(Ap, r1i, c1i, 0);
    pb[0] = ldcvt(Wp, r0i, c0i, 0); pb[1] = ldcvt(Wp, r1i, c1i, 0);
    store_stage(sa0, sb0);
    __syncthreads();

    #pragma unroll 1
    for (int kt = 0; kt < 8; kt++) {
        if (kt < 7) {
            pa[0] = ldcvt(Ap, r0i, c0i, kt + 1); pa[1] = ldcvt(Ap, r1i, c1i, kt + 1);
            pb[0] = ldcvt(Wp, r0i, c0i, kt + 1); pb[1] = ldcvt(Wp, r1i, c1i, kt + 1);
        }
        const uint32_t abuf = (kt & 1) ? sa1 : sa0;
        const uint32_t bbuf = (kt & 1) ? sb1 : sb0;

        #pragma unroll
        for (int s = 0; s < 2; s++) {
            uint32_t a[2][4];
            #pragma unroll
            for (int mt = 0; mt < 2; mt++) {
                const int R = warp_m + mt * 16 + (lane & 15);
                const int c = s * 2 + (lane >> 4);
                LDSM_X4(a[mt][0], a[mt][1], a[mt][2], a[mt][3],
                        abuf + tile_off(R, c));
            }
            #pragma unroll
            for (int np = 0; np < 4; np++) {
                const int g = lane >> 3, lr = lane & 7;
                const int Rn = warp_n + np * 16 + ((g >> 1) << 3) + lr;
                const int c = s * 2 + (g & 1);
                uint32_t b[4];
                LDSM_X4(b[0], b[1], b[2], b[3], bbuf + tile_off(Rn, c));
                #pragma unroll
                for (int mt = 0; mt < 2; mt++) {
                    MMA16816(d[mt][np * 2 + 0], a[mt], b[0], b[1]);
                    MMA16816(d[mt][np * 2 + 1], a[mt], b[2], b[3]);
                }
            }
        }
        __syncthreads();
        if (kt < 7) {
            store_stage((kt & 1) ? sa0 : sa1, (kt & 1) ? sb0 : sb1);
            __syncthreads();
        }
    }

    #pragma unroll
    for (int mt = 0; mt < 2; mt++) {
        #pragma unroll
        for (int half = 0; half < 2; half++) {
            const int row = m0 + warp_m + mt * 16 + (lane >> 2) + half * 8;
            const size_t rbase = (size_t)row * CDIM;
            #pragma unroll
            for (int nt = 0; nt < 8; nt++) {
                const int col = n0 + warp_n + nt * 8 + (lane & 3) * 2;
                float2 v;
                v.x = d[mt][nt][half * 2 + 0];
                v.y = d[mt][nt][half * 2 + 1];
                *(float2*)(out + rbase + col) = v;
            }
        }
    }
}

// ---------------------------------------------------------------------------
// Attention (unchanged): one CTA per (batch, head). seq=128, e=32.
// ---------------------------------------------------------------------------
#define ATTN_SMEM (128 * 129 * 4 + 2 * 128 * 32 * 4)

__global__ void __launch_bounds__(128)
attn_kernel(const float* __restrict__ Q, const float* __restrict__ Kg,
            const float* __restrict__ Vg, float* __restrict__ O)
{
    extern __shared__ float sm[];
    float*  S  = sm;                               // [128][129]
    float4* K4 = (float4*)(sm + 128 * 129);        // [128][8]
    float4* V4 = K4 + 128 * 8;                     // [128][8]

    const int bh = blockIdx.x;
    const int batch = bh >> 3;
    const int head  = bh & 7;
    const size_t r0 = (size_t)batch * 128;
    const int c0 = head * 32;
    const int tid = threadIdx.x;

    for (int idx = tid; idx < 1024; idx += 128) {
        const int j = idx >> 3, e4 = idx & 7;
        K4[idx] = *(const float4*)(Kg + (r0 + j) * CDIM + c0 + e4 * 4);
        V4[idx] = *(const float4*)(Vg + (r0 + j) * CDIM + c0 + e4 * 4);
    }
    float4 q[8];
    #pragma unroll
    for (int e4 = 0; e4 < 8; e4++)
        q[e4] = *(const float4*)(Q + (r0 + tid) * CDIM + c0 + e4 * 4);
    __syncthreads();

    const float sc = 0.17677669529663687f;
    float* Srow = S + tid * 129;

    float mx = -1e30f;
    #pragma unroll 4
    for (int j = 0; j < 128; j++) {
        float d0 = 0.f, d1 = 0.f, d2 = 0.f, d3 = 0.f;
        #pragma unroll
        for (int e4 = 0; e4 < 8; e4++) {
            const float4 kv = K4[j * 8 + e4];
            d0 = fmaf(q[e4].x, kv.x, d0);
            d1 = fmaf(q[e4].y, kv.y, d1);
            d2 = fmaf(q[e4].z, kv.z, d2);
            d3 = fmaf(q[e4].w, kv.w, d3);
        }
        const float d = ((d0 + d1) + (d2 + d3)) * sc;
        Srow[j] = d;
        mx = fmaxf(mx, d);
    }

    float sum = 0.f;
    #pragma unroll 4
    for (int j = 0; j < 128; j++) {
        const float p = __expf(Srow[j] - mx);
        Srow[j] = p;
        sum += p;
    }
    const float inv = 1.f / sum;

    float4 acc[8];
    #pragma unroll
    for (int e4 = 0; e4 < 8; e4++) acc[e4] = make_float4(0.f, 0.f, 0.f, 0.f);
    #pragma unroll 2
    for (int j = 0; j < 128; j++) {
        const float p = Srow[j];
        #pragma unroll
        for (int e4 = 0; e4 < 8; e4++) {
            const float4 v = V4[j * 8 + e4];
            acc[e4].x = fmaf(p, v.x, acc[e4].x);
            acc[e4].y = fmaf(p, v.y, acc[e4].y);
            acc[e4].z = fmaf(p, v.z, acc[e4].z);
            acc[e4].w = fmaf(p, v.w, acc[e4].w);
        }
    }
    #pragma unroll
    for (int e4 = 0; e4 < 8; e4++) {
        float4 r;
        r.x = acc[e4].x * inv; r.y = acc[e4].y * inv;
        r.z = acc[e4].z * inv; r.w = acc[e4].w * inv;
        *(float4*)(O + (r0 + tid) * CDIM + c0 + e4 * 4) = r;
    }
}

// ---------------------------------------------------------------------------
// Launch
// ---------------------------------------------------------------------------
extern "C" void kernel_launch(void* const* d_in, const int* in_sizes, int n_in,
                              void* d_out, int out_size)
{
    const float* x      = (const float*)d_in[0];
    const float* ctx    = (const float*)d_in[1];
    const float* Wq     = (const float*)d_in[2];
    const float* Wkv    = (const float*)d_in[3];
    const float* Wout   = (const float*)d_in[4];
    const float* Wscale = (const float*)d_in[5];
    const float* Wshift = (const float*)d_in[6];
    float* out = (float*)d_out;

    float *gq, *gk, *gv, *ga;
    cudaGetSymbolAddress((void**)&gq, g_q);
    cudaGetSymbolAddress((void**)&gk, g_k);
    cudaGetSymbolAddress((void**)&gv, g_v);
    cudaGetSymbolAddress((void**)&ga, g_attn);

    cudaFuncSetAttribute(fused_proj,
                         cudaFuncAttributeMaxDynamicSharedMemorySize, FP_SMEM);
    cudaFuncSetAttribute(attn_kernel,
                         cudaFuncAttributeMaxDynamicSharedMemorySize, ATTN_SMEM);

    // Fused scale/shift/q/k/v projections with FiLM
    fused_proj<<<MROWS / 64, 256, FP_SMEM>>>(x, ctx, Wq, Wkv, Wscale, Wshift,
                                             gq, gk, gv);

    // attention: 1024 batches x 8 heads
    attn_kernel<<<8192, 128, ATTN_SMEM>>>(gq, gk, gv, ga);

    // output projection straight into d_out
    gemm_h16<<<dim3(2, 1024), 256>>>(ga, Wout, out);
}

// round 8
// speedup vs baseline: 1.6987x; 1.6987x over previous
#include <cuda_runtime.h>
#include <cuda_fp16.h>
#include <cstdint>
#include <math.h>

// Fixed shapes: B=8, C=256, H=128, W=128, heads=8, e=32
#define MROWS 131072
#define CDIM  256
#define NELEM (MROWS * CDIM)

// Scratch (allocation-free rule: __device__ globals)
__device__ float g_q[NELEM];
__device__ float g_k[NELEM];
__device__ float g_v[NELEM];
__device__ float g_attn[NELEM];

// ---------------------------------------------------------------------------
// PTX helpers (sm_80-level: ldmatrix + mma.sync only)
// ---------------------------------------------------------------------------
__device__ __forceinline__ uint32_t smem_u32(const void* p) {
    uint32_t a;
    asm("{ .reg .u64 t; cvta.to.shared.u64 t, %1; cvt.u32.u64 %0, t; }"
        : "=r"(a) : "l"(p));
    return a;
}

#define LDSM_X4(r0, r1, r2, r3, addr)                                         \
    asm volatile("ldmatrix.sync.aligned.m8n8.x4.shared.b16 {%0,%1,%2,%3}, [%4];" \
                 : "=r"(r0), "=r"(r1), "=r"(r2), "=r"(r3) : "r"(addr))

#define MMA16816(d, a, b0, b1)                                                \
    asm volatile("mma.sync.aligned.m16n8k16.row.col.f32.f16.f16.f32 "         \
                 "{%0,%1,%2,%3}, {%4,%5,%6,%7}, {%8,%9}, {%0,%1,%2,%3};"      \
                 : "+f"((d)[0]), "+f"((d)[1]), "+f"((d)[2]), "+f"((d)[3])     \
                 : "r"((a)[0]), "r"((a)[1]), "r"((a)[2]), "r"((a)[3]),        \
                   "r"(b0), "r"(b1))

__device__ __forceinline__ uint32_t packh2(float x, float y) {
    __half2 h = __floats2half2_rn(x, y);
    return *(uint32_t*)&h;
}

// Swizzled byte offset for chunk (row, c) of a [rows][32]-fp16 tile
// (pair-rows of 128B; c = 16B chunk index 0..3). Works for rows<=256.
__device__ __forceinline__ uint32_t tile_off(int row, int c) {
    const int pr = row >> 1;
    const int ch = ((row & 1) << 2) | c;
    return (uint32_t)(pr * 128 + ((ch ^ (pr & 7)) << 4));
}

// ---------------------------------------------------------------------------
// Fused projection kernel (unchanged from R7; measured 687us).
// ---------------------------------------------------------------------------
#define FP_SMEM (229376 + 1024)

__global__ void __launch_bounds__(256, 1)
fused_proj(const float* __restrict__ x, const float* __restrict__ ctx,
           const float* __restrict__ Wq, const float* __restrict__ Wkv,
           const float* __restrict__ Wscale, const float* __restrict__ Wshift,
           float* __restrict__ outq, float* __restrict__ outk,
           float* __restrict__ outv)
{
    extern __shared__ uint8_t smraw[];
    const uint32_t base = (smem_u32(smraw) + 1023u) & ~1023u;
    const uint32_t XT  = base;
    const uint32_t CT  = base + 32768;
    const uint32_t WB0 = base + 65536;
    const uint32_t WB1 = base + 81920;
    const uint32_t SC  = base + 98304;
    const uint32_t SH  = base + 163840;

    const int tid = threadIdx.x, wid = tid >> 5, lane = tid & 31;
    const int m0 = blockIdx.x * 64;
    const int warp_m = (wid & 1) * 32;
    const int warp_n = (wid >> 1) * 64;

    {
        const float* xp = x   + (size_t)m0 * CDIM;
        const float* cp = ctx + (size_t)m0 * CDIM;
        #pragma unroll
        for (int i = 0; i < 8; i++) {
            const int unit = i * 256 + tid;
            const int row = unit >> 5, u = unit & 31;
            const int kc = u >> 2, c = u & 3;
            const uint32_t so = (uint32_t)(kc * 4096) + tile_off(row, c);
            const float4* p = (const float4*)(xp + row * CDIM + u * 8);
            float4 f0 = p[0], f1 = p[1];
            uint4 v;
            v.x = packh2(f0.x, f0.y); v.y = packh2(f0.z, f0.w);
            v.z = packh2(f1.x, f1.y); v.w = packh2(f1.z, f1.w);
            asm volatile("st.shared.v4.b32 [%0], {%1,%2,%3,%4};" ::
                "r"(XT + so), "r"(v.x), "r"(v.y), "r"(v.z), "r"(v.w) : "memory");
            p = (const float4*)(cp + row * CDIM + u * 8);
            f0 = p[0]; f1 = p[1];
            v.x = packh2(f0.x, f0.y); v.y = packh2(f0.z, f0.w);
            v.z = packh2(f1.x, f1.y); v.w = packh2(f1.z, f1.w);
            asm volatile("st.shared.v4.b32 [%0], {%1,%2,%3,%4};" ::
                "r"(CT + so), "r"(v.x), "r"(v.y), "r"(v.z), "r"(v.w) : "memory");
        }
    }
    __syncthreads();

    uint4 pw[4];
    auto ldw = [&](const float* Wp, int kt) {
        #pragma unroll
        for (int i = 0; i < 4; i++) {
            const int idx = i * 256 + tid;
            const int row = idx >> 2, c = idx & 3;
            const float4* p = (const float4*)(Wp + (size_t)row * CDIM + kt * 32 + c * 8);
            const float4 f0 = p[0], f1 = p[1];
            pw[i].x = packh2(f0.x, f0.y); pw[i].y = packh2(f0.z, f0.w);
            pw[i].z = packh2(f1.x, f1.y); pw[i].w = packh2(f1.z, f1.w);
        }
    };
    auto stw = [&](uint32_t buf) {
        #pragma unroll
        for (int i = 0; i < 4; i++) {
            const int idx = i * 256 + tid;
            const int row = idx >> 2, c = idx & 3;
            asm volatile("st.shared.v4.b32 [%0], {%1,%2,%3,%4};" ::
                "r"(buf + tile_off(row, c)),
                "r"(pw[i].x), "r"(pw[i].y), "r"(pw[i].z), "r"(pw[i].w) : "memory");
        }
    };

    float d[2][8][4];
    auto do_gemm = [&](const float* Wp, uint32_t at) {
        #pragma unroll
        for (int mt = 0; mt < 2; mt++)
            #pragma unroll
            for (int nt = 0; nt < 8; nt++)
                #pragma unroll
                for (int i = 0; i < 4; i++) d[mt][nt][i] = 0.f;
        ldw(Wp, 0); stw(WB0);
        __syncthreads();
        #pragma unroll 1
        for (int kt = 0; kt < 8; kt++) {
            if (kt < 7) ldw(Wp, kt + 1);
            const uint32_t wb = (kt & 1) ? WB1 : WB0;
            const uint32_t ac = at + kt * 4096;
            #pragma unroll
            for (int s = 0; s < 2; s++) {
                uint32_t a[2][4];
                #pragma unroll
                for (int mt = 0; mt < 2; mt++) {
                    const int R = warp_m + mt * 16 + (lane & 15);
                    const int c = s * 2 + (lane >> 4);
                    LDSM_X4(a[mt][0], a[mt][1], a[mt][2], a[mt][3],
                            ac + tile_off(R, c));
                }
                #pragma unroll
                for (int np = 0; np < 4; np++) {
                    const int g = lane >> 3, lr = lane & 7;
                    const int Rn = warp_n + np * 16 + ((g >> 1) << 3) + lr;
                    const int c = s * 2 + (g & 1);
                    uint32_t b[4];
                    LDSM_X4(b[0], b[1], b[2], b[3], wb + tile_off(Rn, c));
                    #pragma unroll
                    for (int mt = 0; mt < 2; mt++) {
                        MMA16816(d[mt][np * 2 + 0], a[mt], b[0], b[1]);
                        MMA16816(d[mt][np * 2 + 1], a[mt], b[2], b[3]);
                    }
                }
            }
            __syncthreads();
            if (kt < 7) { stw((kt & 1) ? WB0 : WB1); __syncthreads(); }
        }
    };

    auto smoff = [&](int row, int col) -> uint32_t {
        const int colp = (col + row * 8) & 255;
        return (uint32_t)(row * 1024 + colp * 4);
    };

    const float* Wmats[2] = {Wscale, Wshift};
    const uint32_t Sm[2] = {SC, SH};
    #pragma unroll 1
    for (int mphase = 0; mphase < 2; mphase++) {
        do_gemm(Wmats[mphase], CT);
        #pragma unroll
        for (int mt = 0; mt < 2; mt++)
            #pragma unroll
            for (int half = 0; half < 2; half++) {
                const int row = warp_m + mt * 16 + (lane >> 2) + half * 8;
                #pragma unroll
                for (int nt = 0; nt < 8; nt++) {
                    const int col = warp_n + nt * 8 + (lane & 3) * 2;
                    asm volatile("st.shared.v2.b32 [%0], {%1,%2};" ::
                        "r"(Sm[mphase] + smoff(row, col)),
                        "r"(__float_as_uint(d[mt][nt][half * 2 + 0])),
                        "r"(__float_as_uint(d[mt][nt][half * 2 + 1])) : "memory");
                }
            }
        __syncthreads();
    }

    const float* Wqkv[3] = {Wq, Wkv, Wkv + 256 * CDIM};
    float* Outs[3] = {outq, outk, outv};
    #pragma unroll 1
    for (int mphase = 0; mphase < 3; mphase++) {
        do_gemm(Wqkv[mphase], XT);
        float* outp = Outs[mphase];
        #pragma unroll
        for (int mt = 0; mt < 2; mt++)
            #pragma unroll
            for (int half = 0; half < 2; half++) {
                const int row = warp_m + mt * 16 + (lane >> 2) + half * 8;
                const size_t rbase = (size_t)(m0 + row) * CDIM;
                #pragma unroll
                for (int nt = 0; nt < 8; nt++) {
                    const int col = warp_n + nt * 8 + (lane & 3) * 2;
                    uint32_t sx, sy, tx, ty;
                    asm volatile("ld.shared.v2.b32 {%0,%1}, [%2];"
                        : "=r"(sx), "=r"(sy) : "r"(SC + smoff(row, col)));
                    asm volatile("ld.shared.v2.b32 {%0,%1}, [%2];"
                        : "=r"(tx), "=r"(ty) : "r"(SH + smoff(row, col)));
                    float2 v;
                    v.x = fmaf(__uint_as_float(sx), d[mt][nt][half * 2 + 0],
                               __uint_as_float(tx));
                    v.y = fmaf(__uint_as_float(sy), d[mt][nt][half * 2 + 1],
                               __uint_as_float(ty));
                    *(float2*)(outp + rbase + col) = v;
                }
            }
        __syncthreads();
    }
}

// ---------------------------------------------------------------------------
// Plain fp16 tensor-core GEMM (out-projection): out = A @ W^T, K=256.
// ---------------------------------------------------------------------------
__global__ void __launch_bounds__(256)
gemm_h16(const float* __restrict__ A, const float* __restrict__ W,
         float* __restrict__ out)
{
    constexpr int K = 256;
    __shared__ alignas(128) uint8_t sA[2][8192];
    __shared__ alignas(128) uint8_t sB[2][8192];

    const int tid  = threadIdx.x;
    const int wid  = tid >> 5;
    const int lane = tid & 31;
    const int m0 = blockIdx.y * 128;
    const int n0 = blockIdx.x * 128;

    const int warp_m = (wid & 3) * 32;
    const int warp_n = (wid >> 2) * 64;

    const uint32_t sa0 = smem_u32(&sA[0][0]);
    const uint32_t sa1 = smem_u32(&sA[1][0]);
    const uint32_t sb0 = smem_u32(&sB[0][0]);
    const uint32_t sb1 = smem_u32(&sB[1][0]);

    const int r0i = tid >> 2, c0i = tid & 3;
    const int r1i = (tid + 256) >> 2, c1i = tid & 3;
    const float* Ap = A + (size_t)m0 * K;
    const float* Wp = W + (size_t)n0 * K;

    float d[2][8][4];
    #pragma unroll
    for (int mt = 0; mt < 2; mt++)
        #pragma unroll
        for (int nt = 0; nt < 8; nt++)
            #pragma unroll
            for (int i = 0; i < 4; i++) d[mt][nt][i] = 0.f;

    uint4 pa[2], pb[2];
    auto ldcvt = [&](const float* base, int row, int c, int kt) -> uint4 {
        const float4* p = (const float4*)(base + (size_t)row * K + kt * 32 + c * 8);
        const float4 f0 = p[0], f1 = p[1];
        uint4 u;
        u.x = packh2(f0.x, f0.y); u.y = packh2(f0.z, f0.w);
        u.z = packh2(f1.x, f1.y); u.w = packh2(f1.z, f1.w);
        return u;
    };
    auto store_stage = [&](uint32_t abuf, uint32_t bbuf) {
        asm volatile("st.shared.v4.b32 [%0], {%1,%2,%3,%4};" ::
            "r"(abuf + tile_off(r0i, c0i)), "r"(pa[0].x), "r"(pa[0].y), "r"(pa[0].z), "r"(pa[0].w) : "memory");
        asm volatile("st.shared.v4.b32 [%0], {%1,%2,%3,%4};" ::
            "r"(abuf + tile_off(r1i, c1i)), "r"(pa[1].x), "r"(pa[1].y), "r"(pa[1].z), "r"(pa[1].w) : "memory");
        asm volatile("st.shared.v4.b32 [%0], {%1,%2,%3,%4};" ::
            "r"(bbuf + tile_off(r0i, c0i)), "r"(pb[0].x), "r"(pb[0].y), "r"(pb[0].z), "r"(pb[0].w) : "memory");
        asm volatile("st.shared.v4.b32 [%0], {%1,%2,%3,%4};" ::
            "r"(bbuf + tile_off(r1i, c1i)), "r"(pb[1].x), "r"(pb[1].y), "r"(pb[1].z), "r"(pb[1].w) : "memory");
    };

    pa[0] = ldcvt(Ap, r0i, c0i, 0); pa[1] = ldcvt(Ap, r1i, c1i, 0);
    pb[0] = ldcvt(Wp, r0i, c0i, 0); pb[1] = ldcvt(Wp, r1i, c1i, 0);
    store_stage(sa0, sb0);
    __syncthreads();

    #pragma unroll 1
    for (int kt = 0; kt < 8; kt++) {
        if (kt < 7) {
            pa[0] = ldcvt(Ap, r0i, c0i, kt + 1); pa[1] = ldcvt(Ap, r1i, c1i, kt + 1);
            pb[0] = ldcvt(Wp, r0i, c0i, kt + 1); pb[1] = ldcvt(Wp, r1i, c1i, kt + 1);
        }
        const uint32_t abuf = (kt & 1) ? sa1 : sa0;
        const uint32_t bbuf = (kt & 1) ? sb1 : sb0;

        #pragma unroll
        for (int s = 0; s < 2; s++) {
            uint32_t a[2][4];
            #pragma unroll
            for (int mt = 0; mt < 2; mt++) {
                const int R = warp_m + mt * 16 + (lane & 15);
                const int c = s * 2 + (lane >> 4);
                LDSM_X4(a[mt][0], a[mt][1], a[mt][2], a[mt][3],
                        abuf + tile_off(R, c));
            }
            #pragma unroll
            for (int np = 0; np < 4; np++) {
                const int g = lane >> 3, lr = lane & 7;
                const int Rn = warp_n + np * 16 + ((g >> 1) << 3) + lr;
                const int c = s * 2 + (g & 1);
                uint32_t b[4];
                LDSM_X4(b[0], b[1], b[2], b[3], bbuf + tile_off(Rn, c));
                #pragma unroll
                for (int mt = 0; mt < 2; mt++) {
                    MMA16816(d[mt][np * 2 + 0], a[mt], b[0], b[1]);
                    MMA16816(d[mt][np * 2 + 1], a[mt], b[2], b[3]);
                }
            }
        }
        __syncthreads();
        if (kt < 7) {
            store_stage((kt & 1) ? sa0 : sa1, (kt & 1) ? sb0 : sb1);
            __syncthreads();
        }
    }

    #pragma unroll
    for (int mt = 0; mt < 2; mt++) {
        #pragma unroll
        for (int half = 0; half < 2; half++) {
            const int row = m0 + warp_m + mt * 16 + (lane >> 2) + half * 8;
            const size_t rbase = (size_t)row * CDIM;
            #pragma unroll
            for (int nt = 0; nt < 8; nt++) {
                const int col = n0 + warp_n + nt * 8 + (lane & 3) * 2;
                float2 v;
                v.x = d[mt][nt][half * 2 + 0];
                v.y = d[mt][nt][half * 2 + 1];
                *(float2*)(out + rbase + col) = v;
            }
        }
    }
}

// ---------------------------------------------------------------------------
// Tensor-core attention: one CTA (4 warps) per (batch, head). seq=128, e=32.
// QK^T and PV on mma.m16n8k16 fp16/fp32-accum; softmax in registers with
// quad shfl reductions; P round-tripped through smem as fp16.
// smem: sQ[128][32]h 8KB | sK 8KB | sVt 4x[32][32]h 8KB | sP 4x[128][32]h 32KB
// ---------------------------------------------------------------------------
#define AT_SMEM (57344 + 1024)

__global__ void __launch_bounds__(128)
attn_mma(const float* __restrict__ Qg, const float* __restrict__ Kg,
         const float* __restrict__ Vg, float* __restrict__ O)
{
    extern __shared__ uint8_t smraw[];
    const uint32_t base = (smem_u32(smraw) + 1023u) & ~1023u;
    const uint32_t SQ = base;
    const uint32_t SK = base + 8192;
    const uint32_t SVT = base + 16384;   // 4 chunks x 2KB, [32 e][32 j] each
    const uint32_t SP = base + 24576;    // 4 chunks x 8KB, [128 m][32 j] each

    const int tid = threadIdx.x, wid = tid >> 5, lane = tid & 31;
    const int bh = blockIdx.x;
    const size_t r0 = (size_t)(bh >> 3) * 128;
    const int c0 = (bh & 7) * 32;
    const int warp_m = wid * 32;

    // ---- Stage Q, K: [128][32] fp32 -> fp16 tiles. 4 threads per row. ----
    {
        const int part = tid & 3;             // 8-float segment within row
        #pragma unroll
        for (int pass = 0; pass < 4; pass++) {
            const int row = (tid >> 2) + pass * 32;
            const float4* qp = (const float4*)(Qg + (r0 + row) * CDIM + c0 + part * 8);
            const float4* kp = (const float4*)(Kg + (r0 + row) * CDIM + c0 + part * 8);
            float4 f0 = qp[0], f1 = qp[1];
            uint4 v;
            v.x = packh2(f0.x, f0.y); v.y = packh2(f0.z, f0.w);
            v.z = packh2(f1.x, f1.y); v.w = packh2(f1.z, f1.w);
            asm volatile("st.shared.v4.b32 [%0], {%1,%2,%3,%4};" ::
                "r"(SQ + tile_off(row, part)), "r"(v.x), "r"(v.y), "r"(v.z), "r"(v.w) : "memory");
            f0 = kp[0]; f1 = kp[1];
            v.x = packh2(f0.x, f0.y); v.y = packh2(f0.z, f0.w);
            v.z = packh2(f1.x, f1.y); v.w = packh2(f1.z, f1.w);
            asm volatile("st.shared.v4.b32 [%0], {%1,%2,%3,%4};" ::
                "r"(SK + tile_off(row, part)), "r"(v.x), "r"(v.y), "r"(v.z), "r"(v.w) : "memory");
        }
        // V transposed: Vt[e][j] (chunk ck = j>>5), fp16 scalar stores.
        #pragma unroll
        for (int pass = 0; pass < 4; pass++) {
            const int j = (tid >> 2) + pass * 32;
            const int e0 = part * 8;
            const float4* vp = (const float4*)(Vg + (r0 + j) * CDIM + c0 + e0);
            const float4 f0 = vp[0], f1 = vp[1];
            const float fv[8] = {f0.x, f0.y, f0.z, f0.w, f1.x, f1.y, f1.z, f1.w};
            const uint32_t cb = SVT + (j >> 5) * 2048;
            const int jc = j & 31;
            #pragma unroll
            for (int i = 0; i < 8; i++) {
                const __half h = __float2half_rn(fv[i]);
                const uint16_t hb = *(const uint16_t*)&h;
                asm volatile("st.shared.b16 [%0], %1;" ::
                    "r"(cb + tile_off(e0 + i, jc >> 3) + (jc & 7) * 2), "h"(hb) : "memory");
            }
        }
    }
    __syncthreads();

    // ---- QK^T: S[warp_m..+32][0..128) in registers ----
    float d[2][16][4];
    #pragma unroll
    for (int mt = 0; mt < 2; mt++)
        #pragma unroll
        for (int nt = 0; nt < 16; nt++)
            #pragma unroll
            for (int i = 0; i < 4; i++) d[mt][nt][i] = 0.f;

    #pragma unroll
    for (int s = 0; s < 2; s++) {            // two k16 steps over e=32
        uint32_t a[2][4];
        #pragma unroll
        for (int mt = 0; mt < 2; mt++) {
            const int R = warp_m + mt * 16 + (lane & 15);
            const int c = s * 2 + (lane >> 4);
            LDSM_X4(a[mt][0], a[mt][1], a[mt][2], a[mt][3], SQ + tile_off(R, c));
        }
        #pragma unroll
        for (int np = 0; np < 8; np++) {
            const int g = lane >> 3, lr = lane & 7;
            const int Rn = np * 16 + ((g >> 1) << 3) + lr;
            const int c = s * 2 + (g & 1);
            uint32_t b[4];
            LDSM_X4(b[0], b[1], b[2], b[3], SK + tile_off(Rn, c));
            #pragma unroll
            for (int mt = 0; mt < 2; mt++) {
                MMA16816(d[mt][np * 2 + 0], a[mt], b[0], b[1]);
                MMA16816(d[mt][np * 2 + 1], a[mt], b[2], b[3]);
            }
        }
    }

    // ---- Softmax over each row (row = warp_m + mt*16 + (lane>>2) + half*8).
    // 4 lanes (quad) share a row; reduce via shfl.xor 1,2. P -> smem fp16. ----
    const float sc = 0.17677669529663687f;   // 1/sqrt(32)
    float inv[2][2];
    #pragma unroll
    for (int mt = 0; mt < 2; mt++) {
        #pragma unroll
        for (int half = 0; half < 2; half++) {
            float mx = -1e30f;
            #pragma unroll
            for (int nt = 0; nt < 16; nt++) {
                mx = fmaxf(mx, fmaxf(d[mt][nt][half * 2], d[mt][nt][half * 2 + 1]));
            }
            mx = fmaxf(mx, __shfl_xor_sync(0xffffffffu, mx, 1));
            mx = fmaxf(mx, __shfl_xor_sync(0xffffffffu, mx, 2));
            const float mxs = mx * sc;
            float sum = 0.f;
            const int row = warp_m + mt * 16 + (lane >> 2) + half * 8;
            #pragma unroll
            for (int nt = 0; nt < 16; nt++) {
                const float p0 = __expf(fmaf(d[mt][nt][half * 2 + 0], sc, -mxs));
                const float p1 = __expf(fmaf(d[mt][nt][half * 2 + 1], sc, -mxs));
                sum += p0 + p1;
                const int jc = (nt & 3) * 8 + (lane & 3) * 2;
                asm volatile("st.shared.b32 [%0], %1;" ::
                    "r"(SP + (nt >> 2) * 8192 + tile_off(row, jc >> 3) + (jc & 7) * 2),
                    "r"(packh2(p0, p1)) : "memory");
            }
            sum += __shfl_xor_sync(0xffffffffu, sum, 1);
            sum += __shfl_xor_sync(0xffffffffu, sum, 2);
            inv[mt][half] = 1.f / sum;
        }
    }
    __syncwarp();   // own warp's P rows are read back only by this warp

    // ---- PV: O[warp rows][32] = P @ V ----
    float o[2][4][4];
    #pragma unroll
    for (int mt = 0; mt < 2; mt++)
        #pragma unroll
        for (int nt = 0; nt < 4; nt++)
            #pragma unroll
            for (int i = 0; i < 4; i++) o[mt][nt][i] = 0.f;

    #pragma unroll
    for (int ck = 0; ck < 4; ck++) {          // j chunks of 32
        const uint32_t pb = SP + ck * 8192;
        const uint32_t vb = SVT + ck * 2048;
        #pragma unroll
        for (int s = 0; s < 2; s++) {
            uint32_t a[2][4];
            #pragma unroll
            for (int mt = 0; mt < 2; mt++) {
                const int R = warp_m + mt * 16 + (lane & 15);
                const int c = s * 2 + (lane >> 4);
                LDSM_X4(a[mt][0], a[mt][1], a[mt][2], a[mt][3], pb + tile_off(R, c));
            }
            #pragma unroll
            for (int np = 0; np < 2; np++) {   // e rows 0..31 of Vt
                const int g = lane >> 3, lr = lane & 7;
                const int Rn = np * 16 + ((g >> 1) << 3) + lr;
                const int c = s * 2 + (g & 1);
                uint32_t b[4];
                LDSM_X4(b[0], b[1], b[2], b[3], vb + tile_off(Rn, c));
                #pragma unroll
                for (int mt = 0; mt < 2; mt++) {
                    MMA16816(o[mt][np * 2 + 0], a[mt], b[0], b[1]);
                    MMA16816(o[mt][np * 2 + 1], a[mt], b[2], b[3]);
                }
            }
        }
    }

    // ---- Epilogue: normalize and store fp32 ----
    #pragma unroll
    for (int mt = 0; mt < 2; mt++) {
        #pragma unroll
        for (int half = 0; half < 2; half++) {
            const int row = warp_m + mt * 16 + (lane >> 2) + half * 8;
            const float iv = inv[mt][half];
            const size_t rbase = (r0 + row) * CDIM + c0;
            #pragma unroll
            for (int nt = 0; nt < 4; nt++) {
                const int col = nt * 8 + (lane & 3) * 2;
                float2 v;
                v.x = o[mt][nt][half * 2 + 0] * iv;
                v.y = o[mt][nt][half * 2 + 1] * iv;
                *(float2*)(O + rbase + col) = v;
            }
        }
    }
}

// ---------------------------------------------------------------------------
// Launch
// ---------------------------------------------------------------------------
extern "C" void kernel_launch(void* const* d_in, const int* in_sizes, int n_in,
                              void* d_out, int out_size)
{
    const float* x      = (const float*)d_in[0];
    const float* ctx    = (const float*)d_in[1];
    const float* Wq     = (const float*)d_in[2];
    const float* Wkv    = (const float*)d_in[3];
    const float* Wout   = (const float*)d_in[4];
    const float* Wscale = (const float*)d_in[5];
    const float* Wshift = (const float*)d_in[6];
    float* out = (float*)d_out;

    float *gq, *gk, *gv, *ga;
    cudaGetSymbolAddress((void**)&gq, g_q);
    cudaGetSymbolAddress((void**)&gk, g_k);
    cudaGetSymbolAddress((void**)&gv, g_v);
    cudaGetSymbolAddress((void**)&ga, g_attn);

    cudaFuncSetAttribute(fused_proj,
                         cudaFuncAttributeMaxDynamicSharedMemorySize, FP_SMEM);
    cudaFuncSetAttribute(attn_mma,
                         cudaFuncAttributeMaxDynamicSharedMemorySize, AT_SMEM);

    // Fused scale/shift/q/k/v projections with FiLM
    fused_proj<<<MROWS / 64, 256, FP_SMEM>>>(x, ctx, Wq, Wkv, Wscale, Wshift,
                                             gq, gk, gv);

    // attention: 1024 batches x 8 heads, tensor-core
    attn_mma<<<8192, 128, AT_SMEM>>>(gq, gk, gv, ga);

    // output projection straight into d_out
    gemm_h16<<<dim3(2, 1024), 256>>>(ga, Wout, out);
}

// round 9
// speedup vs baseline: 2.0370x; 1.1991x over previous
#include <cuda_runtime.h>
#include <cuda_fp16.h>
#include <cstdint>
#include <math.h>

// Fixed shapes: B=8, C=256, H=128, W=128, heads=8, e=32
#define MROWS 131072
#define CDIM  256
#define NELEM (MROWS * CDIM)

// Scratch (allocation-free rule: __device__ globals)
__device__ float g_q[NELEM];
__device__ float g_k[NELEM];
__device__ float g_v[NELEM];
__device__ float g_attn[NELEM];
// Preconverted fp16 weights, swizzled chunk-major:
// 6 mats x 8 ksteps x [256 rows][32 cols] fp16 (16KB blocks)
// mats: 0=Wscale 1=Wshift 2=Wq 3=Wk 4=Wv 5=Wout
__device__ __align__(16) uint16_t g_wh[6 * 8 * 8192];

// ---------------------------------------------------------------------------
// PTX helpers (sm_80-level: ldmatrix + mma.sync + cp.async)
// ---------------------------------------------------------------------------
__device__ __forceinline__ uint32_t smem_u32(const void* p) {
    uint32_t a;
    asm("{ .reg .u64 t; cvta.to.shared.u64 t, %1; cvt.u32.u64 %0, t; }"
        : "=r"(a) : "l"(p));
    return a;
}

#define LDSM_X4(r0, r1, r2, r3, addr)                                         \
    asm volatile("ldmatrix.sync.aligned.m8n8.x4.shared.b16 {%0,%1,%2,%3}, [%4];" \
                 : "=r"(r0), "=r"(r1), "=r"(r2), "=r"(r3) : "r"(addr))

#define MMA16816(d, a, b0, b1)                                                \
    asm volatile("mma.sync.aligned.m16n8k16.row.col.f32.f16.f16.f32 "         \
                 "{%0,%1,%2,%3}, {%4,%5,%6,%7}, {%8,%9}, {%0,%1,%2,%3};"      \
                 : "+f"((d)[0]), "+f"((d)[1]), "+f"((d)[2]), "+f"((d)[3])     \
                 : "r"((a)[0]), "r"((a)[1]), "r"((a)[2]), "r"((a)[3]),        \
                   "r"(b0), "r"(b1))

#define CP_ASYNC16(dst, src)                                                  \
    asm volatile("cp.async.cg.shared.global [%0], [%1], 16;" ::               \
                 "r"(dst), "l"(src) : "memory")
#define CP_COMMIT()  asm volatile("cp.async.commit_group;" ::: "memory")
#define CP_WAIT0()   asm volatile("cp.async.wait_group 0;" ::: "memory")

__device__ __forceinline__ uint32_t packh2(float x, float y) {
    __half2 h = __floats2half2_rn(x, y);
    return *(uint32_t*)&h;
}

// Swizzled byte offset for chunk (row, c) of a [rows][32]-fp16 tile
// (pair-rows of 128B; c = 16B chunk index 0..3). Works for rows<=256.
__device__ __forceinline__ uint32_t tile_off(int row, int c) {
    const int pr = row >> 1;
    const int ch = ((row & 1) << 2) | c;
    return (uint32_t)(pr * 128 + ((ch ^ (pr & 7)) << 4));
}

// ---------------------------------------------------------------------------
// Weight preconversion: fp32 -> fp16 in swizzled chunk-major layout.
// grid 48 (= 6 mats x 8 ksteps), 256 threads.
// ---------------------------------------------------------------------------
__global__ void __launch_bounds__(256)
wcvt(const float* __restrict__ Wq, const float* __restrict__ Wkv,
     const float* __restrict__ Wscale, const float* __restrict__ Wshift,
     const float* __restrict__ Wout)
{
    const int blk = blockIdx.x;
    const int mat = blk >> 3, kt = blk & 7;
    const float* srcs[6] = {Wscale, Wshift, Wq, Wkv, Wkv + 65536, Wout};
    const float* src = srcs[mat];
    uint8_t* dst = (uint8_t*)g_wh + (size_t)blk * 16384;
    for (int i = threadIdx.x; i < 8192; i += 256) {
        const int r = i >> 5, col = i & 31;
        const __half h = __float2half_rn(src[r * 256 + kt * 32 + col]);
        *(__half*)(dst + tile_off(r, col >> 3) + (col & 7) * 2) = h;
    }
}

// ---------------------------------------------------------------------------
// Fused projection kernel v3. Per CTA: 64 rows of the flat (M,256) view.
// Weights stream as cp.async byte-copies of preconverted fp16 blocks:
// no register staging, one __syncthreads per k-step.
// ---------------------------------------------------------------------------
#define FP_SMEM (229376 + 1024)

// smem map (from 1024-aligned base):
//  XT  : 0      .. 32KB   x tile, 8 chunks x [64][32] fp16
//  CT  : 32KB   .. 64KB   ctx tile
//  WB0 : 64KB   .. 80KB   weight stage 0 ([256][32] fp16)
//  WB1 : 80KB   .. 96KB   weight stage 1
//  SC  : 96KB   .. 160KB  scale [64][256] fp32, shifted cols
//  SH  : 160KB  .. 224KB  shift

__global__ void __launch_bounds__(256, 1)
fused_proj(const float* __restrict__ x, const float* __restrict__ ctx,
           float* __restrict__ outq, float* __restrict__ outk,
           float* __restrict__ outv)
{
    extern __shared__ uint8_t smraw[];
    const uint32_t base = (smem_u32(smraw) + 1023u) & ~1023u;
    const uint32_t XT  = base;
    const uint32_t CT  = base + 32768;
    const uint32_t WB0 = base + 65536;
    const uint32_t WB1 = base + 81920;
    const uint32_t SC  = base + 98304;
    const uint32_t SH  = base + 163840;

    const int tid = threadIdx.x, wid = tid >> 5, lane = tid & 31;
    const int m0 = blockIdx.x * 64;
    const int warp_m = (wid & 1) * 32;   // 2 warps down M (64)
    const int warp_n = (wid >> 1) * 64;  // 4 warps across N (256)

    // ---- Stage x & ctx tiles: 64 rows x 256 fp32 -> fp16 chunk-major ----
    {
        const float* xp = x   + (size_t)m0 * CDIM;
        const float* cp = ctx + (size_t)m0 * CDIM;
        #pragma unroll
        for (int i = 0; i < 8; i++) {
            const int unit = i * 256 + tid;       // 2048 units of 8 floats
            const int row = unit >> 5, u = unit & 31;
            const int kc = u >> 2, c = u & 3;
            const uint32_t so = (uint32_t)(kc * 4096) + tile_off(row, c);
            const float4* p = (const float4*)(xp + row * CDIM + u * 8);
            float4 f0 = p[0], f1 = p[1];
            uint4 v;
            v.x = packh2(f0.x, f0.y); v.y = packh2(f0.z, f0.w);
            v.z = packh2(f1.x, f1.y); v.w = packh2(f1.z, f1.w);
            asm volatile("st.shared.v4.b32 [%0], {%1,%2,%3,%4};" ::
                "r"(XT + so), "r"(v.x), "r"(v.y), "r"(v.z), "r"(v.w) : "memory");
            p = (const float4*)(cp + row * CDIM + u * 8);
            f0 = p[0]; f1 = p[1];
            v.x = packh2(f0.x, f0.y); v.y = packh2(f0.z, f0.w);
            v.z = packh2(f1.x, f1.y); v.w = packh2(f1.z, f1.w);
            asm volatile("st.shared.v4.b32 [%0], {%1,%2,%3,%4};" ::
                "r"(CT + so), "r"(v.x), "r"(v.y), "r"(v.z), "r"(v.w) : "memory");
        }
    }
    __syncthreads();

    // cp.async weight stage: 16KB block, 256 threads x 64B.
    auto ldw_async = [&](int mat, int kt, uint32_t buf) {
        const uint8_t* src = (const uint8_t*)g_wh
                           + ((size_t)(mat * 8 + kt) << 14) + tid * 64;
        const uint32_t d0 = buf + tid * 64;
        CP_ASYNC16(d0,      src);
        CP_ASYNC16(d0 + 16, src + 16);
        CP_ASYNC16(d0 + 32, src + 32);
        CP_ASYNC16(d0 + 48, src + 48);
        CP_COMMIT();
    };

    float d[2][8][4];
    auto do_gemm = [&](int mat, uint32_t at) {
        #pragma unroll
        for (int mt = 0; mt < 2; mt++)
            #pragma unroll
            for (int nt = 0; nt < 8; nt++)
                #pragma unroll
                for (int i = 0; i < 4; i++) d[mt][nt][i] = 0.f;
        ldw_async(mat, 0, WB0);
        #pragma unroll 1
        for (int kt = 0; kt < 8; kt++) {
            CP_WAIT0();              // weight stage kt landed
            __syncthreads();         // visible to all; prior MMA certified done
            if (kt < 7) ldw_async(mat, kt + 1, (kt & 1) ? WB0 : WB1);
            const uint32_t wb = (kt & 1) ? WB1 : WB0;
            const uint32_t ac = at + kt * 4096;
            #pragma unroll
            for (int s = 0; s < 2; s++) {
                uint32_t a[2][4];
                #pragma unroll
                for (int mt = 0; mt < 2; mt++) {
                    const int R = warp_m + mt * 16 + (lane & 15);
                    const int c = s * 2 + (lane >> 4);
                    LDSM_X4(a[mt][0], a[mt][1], a[mt][2], a[mt][3],
                            ac + tile_off(R, c));
                }
                #pragma unroll
                for (int np = 0; np < 4; np++) {
                    const int g = lane >> 3, lr = lane & 7;
                    const int Rn = warp_n + np * 16 + ((g >> 1) << 3) + lr;
                    const int c = s * 2 + (g & 1);
                    uint32_t b[4];
                    LDSM_X4(b[0], b[1], b[2], b[3], wb + tile_off(Rn, c));
                    #pragma unroll
                    for (int mt = 0; mt < 2; mt++) {
                        MMA16816(d[mt][np * 2 + 0], a[mt], b[0], b[1]);
                        MMA16816(d[mt][np * 2 + 1], a[mt], b[2], b[3]);
                    }
                }
            }
        }
    };

    // shifted fp32 [64][256] smem accessors (write/read same-thread)
    auto smoff = [&](int row, int col) -> uint32_t {
        const int colp = (col + row * 8) & 255;
        return (uint32_t)(row * 1024 + colp * 4);
    };

    // ---- scale, shift (from ctx tile) -> smem ----
    const uint32_t Sm[2] = {SC, SH};
    #pragma unroll 1
    for (int mphase = 0; mphase < 2; mphase++) {
        do_gemm(mphase, CT);                 // mat 0=Wscale, 1=Wshift
        #pragma unroll
        for (int mt = 0; mt < 2; mt++)
            #pragma unroll
            for (int half = 0; half < 2; half++) {
                const int row = warp_m + mt * 16 + (lane >> 2) + half * 8;
                #pragma unroll
                for (int nt = 0; nt < 8; nt++) {
                    const int col = warp_n + nt * 8 + (lane & 3) * 2;
                    asm volatile("st.shared.v2.b32 [%0], {%1,%2};" ::
                        "r"(Sm[mphase] + smoff(row, col)),
                        "r"(__float_as_uint(d[mt][nt][half * 2 + 0])),
                        "r"(__float_as_uint(d[mt][nt][half * 2 + 1])) : "memory");
                }
            }
        __syncthreads();
    }

    // ---- q, k, v (from x tile) with fused FiLM ----
    float* Outs[3] = {outq, outk, outv};
    #pragma unroll 1
    for (int mphase = 0; mphase < 3; mphase++) {
        do_gemm(2 + mphase, XT);             // mats 2=Wq, 3=Wk, 4=Wv
        float* outp = Outs[mphase];
        #pragma unroll
        for (int mt = 0; mt < 2; mt++)
            #pragma unroll
            for (int half = 0; half < 2; half++) {
                const int row = warp_m + mt * 16 + (lane >> 2) + half * 8;
                const size_t rbase = (size_t)(m0 + row) * CDIM;
                #pragma unroll
                for (int nt = 0; nt < 8; nt++) {
                    const int col = warp_n + nt * 8 + (lane & 3) * 2;
                    uint32_t sx, sy, tx, ty;
                    asm volatile("ld.shared.v2.b32 {%0,%1}, [%2];"
                        : "=r"(sx), "=r"(sy) : "r"(SC + smoff(row, col)));
                    asm volatile("ld.shared.v2.b32 {%0,%1}, [%2];"
                        : "=r"(tx), "=r"(ty) : "r"(SH + smoff(row, col)));
                    float2 v;
                    v.x = fmaf(__uint_as_float(sx), d[mt][nt][half * 2 + 0],
                               __uint_as_float(tx));
                    v.y = fmaf(__uint_as_float(sy), d[mt][nt][half * 2 + 1],
                               __uint_as_float(ty));
                    *(float2*)(outp + rbase + col) = v;
                }
            }
        __syncthreads();
    }
}

// ---------------------------------------------------------------------------
// Out-projection GEMM v2: out = A @ Wout^T, K=256. A fp32 staged in regs;
// B = preconverted fp16 Wout blocks via cp.async (sub-tile at n0 is a
// contiguous n0*64-byte offset inside each 16KB block).
// ---------------------------------------------------------------------------
__global__ void __launch_bounds__(256)
gemm_h16(const float* __restrict__ A, float* __restrict__ out)
{
    constexpr int K = 256;
    __shared__ alignas(128) uint8_t sA[2][8192];
    __shared__ alignas(128) uint8_t sB[2][8192];

    const int tid  = threadIdx.x;
    const int wid  = tid >> 5;
    const int lane = tid & 31;
    const int m0 = blockIdx.y * 128;
    const int n0 = blockIdx.x * 128;

    const int warp_m = (wid & 3) * 32;
    const int warp_n = (wid >> 2) * 64;

    const uint32_t sa0 = smem_u32(&sA[0][0]);
    const uint32_t sa1 = smem_u32(&sA[1][0]);
    const uint32_t sb0 = smem_u32(&sB[0][0]);
    const uint32_t sb1 = smem_u32(&sB[1][0]);

    const int r0i = tid >> 2, c0i = tid & 3;
    const int r1i = (tid + 256) >> 2, c1i = tid & 3;
    const float* Ap = A + (size_t)m0 * K;

    float d[2][8][4];
    #pragma unroll
    for (int mt = 0; mt < 2; mt++)
        #pragma unroll
        for (int nt = 0; nt < 8; nt++)
            #pragma unroll
            for (int i = 0; i < 4; i++) d[mt][nt][i] = 0.f;

    uint4 pa[2];
    auto ldcvt = [&](int row, int c, int kt) -> uint4 {
        const float4* p = (const float4*)(Ap + (size_t)row * K + kt * 32 + c * 8);
        const float4 f0 = p[0], f1 = p[1];
        uint4 u;
        u.x = packh2(f0.x, f0.y); u.y = packh2(f0.z, f0.w);
        u.z = packh2(f1.x, f1.y); u.w = packh2(f1.z, f1.w);
        return u;
    };
    auto stsA = [&](uint32_t abuf) {
        asm volatile("st.shared.v4.b32 [%0], {%1,%2,%3,%4};" ::
            "r"(abuf + tile_off(r0i, c0i)), "r"(pa[0].x), "r"(pa[0].y), "r"(pa[0].z), "r"(pa[0].w) : "memory");
        asm volatile("st.shared.v4.b32 [%0], {%1,%2,%3,%4};" ::
            "r"(abuf + tile_off(r1i, c1i)), "r"(pa[1].x), "r"(pa[1].y), "r"(pa[1].z), "r"(pa[1].w) : "memory");
    };
    // B stage: 8KB = rows [n0, n0+128) of Wout block kt (mat 5).
    auto ldb_async = [&](int kt, uint32_t buf) {
        const uint8_t* src = (const uint8_t*)g_wh + ((size_t)(40 + kt) << 14)
                           + n0 * 64 + tid * 32;
        const uint32_t d0 = buf + tid * 32;
        CP_ASYNC16(d0,      src);
        CP_ASYNC16(d0 + 16, src + 16);
        CP_COMMIT();
    };

    ldb_async(0, sb0);
    pa[0] = ldcvt(r0i, c0i, 0); pa[1] = ldcvt(r1i, c1i, 0);
    stsA(sa0);
    __syncthreads();

    #pragma unroll 1
    for (int kt = 0; kt < 8; kt++) {
        if (kt < 7) { pa[0] = ldcvt(r0i, c0i, kt + 1); pa[1] = ldcvt(r1i, c1i, kt + 1); }
        CP_WAIT0();
        __syncthreads();                       // B kt visible; MMA(kt-1) certified
        if (kt < 7) ldb_async(kt + 1, (kt & 1) ? sb0 : sb1);
        const uint32_t abuf = (kt & 1) ? sa1 : sa0;
        const uint32_t bbuf = (kt & 1) ? sb1 : sb0;

        #pragma unroll
        for (int s = 0; s < 2; s++) {
            uint32_t a[2][4];
            #pragma unroll
            for (int mt = 0; mt < 2; mt++) {
                const int R = warp_m + mt * 16 + (lane & 15);
                const int c = s * 2 + (lane >> 4);
                LDSM_X4(a[mt][0], a[mt][1], a[mt][2], a[mt][3],
                        abuf + tile_off(R, c));
            }
            #pragma unroll
            for (int np = 0; np < 4; np++) {
                const int g = lane >> 3, lr = lane & 7;
                const int Rn = warp_n + np * 16 + ((g >> 1) << 3) + lr;
                const int c = s * 2 + (g & 1);
                uint32_t b[4];
                LDSM_X4(b[0], b[1], b[2], b[3], bbuf + tile_off(Rn, c));
                #pragma unroll
                for (int mt = 0; mt < 2; mt++) {
                    MMA16816(d[mt][np * 2 + 0], a[mt], b[0], b[1]);
                    MMA16816(d[mt][np * 2 + 1], a[mt], b[2], b[3]);
                }
            }
        }
        __syncthreads();                       // MMA(kt) done before A overwrite
        if (kt < 7) stsA((kt & 1) ? sa0 : sa1);
    }

    #pragma unroll
    for (int mt = 0; mt < 2; mt++) {
        #pragma unroll
        for (int half = 0; half < 2; half++) {
            const int row = m0 + warp_m + mt * 16 + (lane >> 2) + half * 8;
            const size_t rbase = (size_t)row * CDIM;
            #pragma unroll
            for (int nt = 0; nt < 8; nt++) {
                const int col = n0 + warp_n + nt * 8 + (lane & 3) * 2;
                float2 v;
                v.x = d[mt][nt][half * 2 + 0];
                v.y = d[mt][nt][half * 2 + 1];
                *(float2*)(out + rbase + col) = v;
            }
        }
    }
}

// ---------------------------------------------------------------------------
// Tensor-core attention (unchanged from R8): one CTA (4 warps) per
// (batch, head). seq=128, e=32.
// ---------------------------------------------------------------------------
#define AT_SMEM (57344 + 1024)

__global__ void __launch_bounds__(128)
attn_mma(const float* __restrict__ Qg, const float* __restrict__ Kg,
         const float* __restrict__ Vg, float* __restrict__ O)
{
    extern __shared__ uint8_t smraw[];
    const uint32_t base = (smem_u32(smraw) + 1023u) & ~1023u;
    const uint32_t SQ = base;
    const uint32_t SK = base + 8192;
    const uint32_t SVT = base + 16384;   // 4 chunks x 2KB, [32 e][32 j] each
    const uint32_t SP = base + 24576;    // 4 chunks x 8KB, [128 m][32 j] each

    const int tid = threadIdx.x, wid = tid >> 5, lane = tid & 31;
    const int bh = blockIdx.x;
    const size_t r0 = (size_t)(bh >> 3) * 128;
    const int c0 = (bh & 7) * 32;
    const int warp_m = wid * 32;

    {
        const int part = tid & 3;
        #pragma unroll
        for (int pass = 0; pass < 4; pass++) {
            const int row = (tid >> 2) + pass * 32;
            const float4* qp = (const float4*)(Qg + (r0 + row) * CDIM + c0 + part * 8);
            const float4* kp = (const float4*)(Kg + (r0 + row) * CDIM + c0 + part * 8);
            float4 f0 = qp[0], f1 = qp[1];
            uint4 v;
            v.x = packh2(f0.x, f0.y); v.y = packh2(f0.z, f0.w);
            v.z = packh2(f1.x, f1.y); v.w = packh2(f1.z, f1.w);
            asm volatile("st.shared.v4.b32 [%0], {%1,%2,%3,%4};" ::
                "r"(SQ + tile_off(row, part)), "r"(v.x), "r"(v.y), "r"(v.z), "r"(v.w) : "memory");
            f0 = kp[0]; f1 = kp[1];
            v.x = packh2(f0.x, f0.y); v.y = packh2(f0.z, f0.w);
            v.z = packh2(f1.x, f1.y); v.w = packh2(f1.z, f1.w);
            asm volatile("st.shared.v4.b32 [%0], {%1,%2,%3,%4};" ::
                "r"(SK + tile_off(row, part)), "r"(v.x), "r"(v.y), "r"(v.z), "r"(v.w) : "memory");
        }
        #pragma unroll
        for (int pass = 0; pass < 4; pass++) {
            const int j = (tid >> 2) + pass * 32;
            const int e0 = part * 8;
            const float4* vp = (const float4*)(Vg + (r0 + j) * CDIM + c0 + e0);
            const float4 f0 = vp[0], f1 = vp[1];
            const float fv[8] = {f0.x, f0.y, f0.z, f0.w, f1.x, f1.y, f1.z, f1.w};
            const uint32_t cb = SVT + (j >> 5) * 2048;
            const int jc = j & 31;
            #pragma unroll
            for (int i = 0; i < 8; i++) {
                const __half h = __float2half_rn(fv[i]);
                const uint16_t hb = *(const uint16_t*)&h;
                asm volatile("st.shared.b16 [%0], %1;" ::
                    "r"(cb + tile_off(e0 + i, jc >> 3) + (jc & 7) * 2), "h"(hb) : "memory");
            }
        }
    }
    __syncthreads();

    float d[2][16][4];
    #pragma unroll
    for (int mt = 0; mt < 2; mt++)
        #pragma unroll
        for (int nt = 0; nt < 16; nt++)
            #pragma unroll
            for (int i = 0; i < 4; i++) d[mt][nt][i] = 0.f;

    #pragma unroll
    for (int s = 0; s < 2; s++) {
        uint32_t a[2][4];
        #pragma unroll
        for (int mt = 0; mt < 2; mt++) {
            const int R = warp_m + mt * 16 + (lane & 15);
            const int c = s * 2 + (lane >> 4);
            LDSM_X4(a[mt][0], a[mt][1], a[mt][2], a[mt][3], SQ + tile_off(R, c));
        }
        #pragma unroll
        for (int np = 0; np < 8; np++) {
            const int g = lane >> 3, lr = lane & 7;
            const int Rn = np * 16 + ((g >> 1) << 3) + lr;
            const int c = s * 2 + (g & 1);
            uint32_t b[4];
            LDSM_X4(b[0], b[1], b[2], b[3], SK + tile_off(Rn, c));
            #pragma unroll
            for (int mt = 0; mt < 2; mt++) {
                MMA16816(d[mt][np * 2 + 0], a[mt], b[0], b[1]);
                MMA16816(d[mt][np * 2 + 1], a[mt], b[2], b[3]);
            }
        }
    }

    const float sc = 0.17677669529663687f;
    float inv[2][2];
    #pragma unroll
    for (int mt = 0; mt < 2; mt++) {
        #pragma unroll
        for (int half = 0; half < 2; half++) {
            float mx = -1e30f;
            #pragma unroll
            for (int nt = 0; nt < 16; nt++) {
                mx = fmaxf(mx, fmaxf(d[mt][nt][half * 2], d[mt][nt][half * 2 + 1]));
            }
            mx = fmaxf(mx, __shfl_xor_sync(0xffffffffu, mx, 1));
            mx = fmaxf(mx, __shfl_xor_sync(0xffffffffu, mx, 2));
            const float mxs = mx * sc;
            float sum = 0.f;
            const int row = warp_m + mt * 16 + (lane >> 2) + half * 8;
            #pragma unroll
            for (int nt = 0; nt < 16; nt++) {
                const float p0 = __expf(fmaf(d[mt][nt][half * 2 + 0], sc, -mxs));
                const float p1 = __expf(fmaf(d[mt][nt][half * 2 + 1], sc, -mxs));
                sum += p0 + p1;
                const int jc = (nt & 3) * 8 + (lane & 3) * 2;
                asm volatile("st.shared.b32 [%0], %1;" ::
                    "r"(SP + (nt >> 2) * 8192 + tile_off(row, jc >> 3) + (jc & 7) * 2),
                    "r"(packh2(p0, p1)) : "memory");
            }
            sum += __shfl_xor_sync(0xffffffffu, sum, 1);
            sum += __shfl_xor_sync(0xffffffffu, sum, 2);
            inv[mt][half] = 1.f / sum;
        }
    }
    __syncwarp();

    float o[2][4][4];
    #pragma unroll
    for (int mt = 0; mt < 2; mt++)
        #pragma unroll
        for (int nt = 0; nt < 4; nt++)
            #pragma unroll
            for (int i = 0; i < 4; i++) o[mt][nt][i] = 0.f;

    #pragma unroll
    for (int ck = 0; ck < 4; ck++) {
        const uint32_t pb = SP + ck * 8192;
        const uint32_t vb = SVT + ck * 2048;
        #pragma unroll
        for (int s = 0; s < 2; s++) {
            uint32_t a[2][4];
            #pragma unroll
            for (int mt = 0; mt < 2; mt++) {
                const int R = warp_m + mt * 16 + (lane & 15);
                const int c = s * 2 + (lane >> 4);
                LDSM_X4(a[mt][0], a[mt][1], a[mt][2], a[mt][3], pb + tile_off(R, c));
            }
            #pragma unroll
            for (int np = 0; np < 2; np++) {
                const int g = lane >> 3, lr = lane & 7;
                const int Rn = np * 16 + ((g >> 1) << 3) + lr;
                const int c = s * 2 + (g & 1);
                uint32_t b[4];
                LDSM_X4(b[0], b[1], b[2], b[3], vb + tile_off(Rn, c));
                #pragma unroll
                for (int mt = 0; mt < 2; mt++) {
                    MMA16816(o[mt][np * 2 + 0], a[mt], b[0], b[1]);
                    MMA16816(o[mt][np * 2 + 1], a[mt], b[2], b[3]);
                }
            }
        }
    }

    #pragma unroll
    for (int mt = 0; mt < 2; mt++) {
        #pragma unroll
        for (int half = 0; half < 2; half++) {
            const int row = warp_m + mt * 16 + (lane >> 2) + half * 8;
            const float iv = inv[mt][half];
            const size_t rbase = (r0 + row) * CDIM + c0;
            #pragma unroll
            for (int nt = 0; nt < 4; nt++) {
                const int col = nt * 8 + (lane & 3) * 2;
                float2 v;
                v.x = o[mt][nt][half * 2 + 0] * iv;
                v.y = o[mt][nt][half * 2 + 1] * iv;
                *(float2*)(O + rbase + col) = v;
            }
        }
    }
}

// ---------------------------------------------------------------------------
// Launch
// ---------------------------------------------------------------------------
extern "C" void kernel_launch(void* const* d_in, const int* in_sizes, int n_in,
                              void* d_out, int out_size)
{
    const float* x      = (const float*)d_in[0];
    const float* ctx    = (const float*)d_in[1];
    const float* Wq     = (const float*)d_in[2];
    const float* Wkv    = (const float*)d_in[3];
    const float* Wout   = (const float*)d_in[4];
    const float* Wscale = (const float*)d_in[5];
    const float* Wshift = (const float*)d_in[6];
    float* out = (float*)d_out;

    float *gq, *gk, *gv, *ga;
    cudaGetSymbolAddress((void**)&gq, g_q);
    cudaGetSymbolAddress((void**)&gk, g_k);
    cudaGetSymbolAddress((void**)&gv, g_v);
    cudaGetSymbolAddress((void**)&ga, g_attn);

    cudaFuncSetAttribute(fused_proj,
                         cudaFuncAttributeMaxDynamicSharedMemorySize, FP_SMEM);
    cudaFuncSetAttribute(attn_mma,
                         cudaFuncAttributeMaxDynamicSharedMemorySize, AT_SMEM);

    // one-time-per-call weight preconversion (fp16, swizzled chunk layout)
    wcvt<<<48, 256>>>(Wq, Wkv, Wscale, Wshift, Wout);

    // Fused scale/shift/q/k/v projections with FiLM
    fused_proj<<<MROWS / 64, 256, FP_SMEM>>>(x, ctx, gq, gk, gv);

    // attention: 1024 batches x 8 heads, tensor-core
    attn_mma<<<8192, 128, AT_SMEM>>>(gq, gk, gv, ga);

    // output projection straight into d_out
    gemm_h16<<<dim3(2, 1024), 256>>>(ga, out);
}

// round 10
// speedup vs baseline: 2.1444x; 1.0528x over previous
#include <cuda_runtime.h>
#include <cuda_fp16.h>
#include <cstdint>
#include <math.h>

// Fixed shapes: B=8, C=256, H=128, W=128, heads=8, e=32
#define MROWS 131072
#define CDIM  256
#define NELEM (MROWS * CDIM)

// Scratch (allocation-free rule: __device__ globals)
__device__ float g_q[NELEM];
__device__ float g_k[NELEM];
__device__ float g_v[NELEM];
__device__ float g_attn[NELEM];
// Preconverted fp16 weights, swizzled chunk-major:
// 6 mats x 8 ksteps x [256 rows][32 cols] fp16 (16KB blocks)
// mats: 0=Wscale 1=Wshift 2=Wq 3=Wk 4=Wv 5=Wout
__device__ __align__(16) uint16_t g_wh[6 * 8 * 8192];

// ---------------------------------------------------------------------------
// PTX helpers (sm_80-level: ldmatrix + mma.sync + cp.async)
// ---------------------------------------------------------------------------
__device__ __forceinline__ uint32_t smem_u32(const void* p) {
    uint32_t a;
    asm("{ .reg .u64 t; cvta.to.shared.u64 t, %1; cvt.u32.u64 %0, t; }"
        : "=r"(a) : "l"(p));
    return a;
}

#define LDSM_X4(r0, r1, r2, r3, addr)                                         \
    asm volatile("ldmatrix.sync.aligned.m8n8.x4.shared.b16 {%0,%1,%2,%3}, [%4];" \
                 : "=r"(r0), "=r"(r1), "=r"(r2), "=r"(r3) : "r"(addr))

#define MMA16816(d, a, b0, b1)                                                \
    asm volatile("mma.sync.aligned.m16n8k16.row.col.f32.f16.f16.f32 "         \
                 "{%0,%1,%2,%3}, {%4,%5,%6,%7}, {%8,%9}, {%0,%1,%2,%3};"      \
                 : "+f"((d)[0]), "+f"((d)[1]), "+f"((d)[2]), "+f"((d)[3])     \
                 : "r"((a)[0]), "r"((a)[1]), "r"((a)[2]), "r"((a)[3]),        \
                   "r"(b0), "r"(b1))

#define CP_ASYNC16(dst, src)                                                  \
    asm volatile("cp.async.cg.shared.global [%0], [%1], 16;" ::               \
                 "r"(dst), "l"(src) : "memory")
#define CP_COMMIT()  asm volatile("cp.async.commit_group;" ::: "memory")
#define CP_WAIT0()   asm volatile("cp.async.wait_group 0;" ::: "memory")

__device__ __forceinline__ uint32_t packh2(float x, float y) {
    __half2 h = __floats2half2_rn(x, y);
    return *(uint32_t*)&h;
}

// Swizzled byte offset for chunk (row, c) of a [rows][32]-fp16 tile
// (pair-rows of 128B; c = 16B chunk index 0..3). Works for rows<=256.
__device__ __forceinline__ uint32_t tile_off(int row, int c) {
    const int pr = row >> 1;
    const int ch = ((row & 1) << 2) | c;
    return (uint32_t)(pr * 128 + ((ch ^ (pr & 7)) << 4));
}

// ---------------------------------------------------------------------------
// Weight preconversion: fp32 -> fp16 in swizzled chunk-major layout.
// ---------------------------------------------------------------------------
__global__ void __launch_bounds__(256)
wcvt(const float* __restrict__ Wq, const float* __restrict__ Wkv,
     const float* __restrict__ Wscale, const float* __restrict__ Wshift,
     const float* __restrict__ Wout)
{
    const int blk = blockIdx.x;
    const int mat = blk >> 3, kt = blk & 7;
    const float* srcs[6] = {Wscale, Wshift, Wq, Wkv, Wkv + 65536, Wout};
    const float* src = srcs[mat];
    uint8_t* dst = (uint8_t*)g_wh + (size_t)blk * 16384;
    for (int i = threadIdx.x; i < 8192; i += 256) {
        const int r = i >> 5, col = i & 31;
        const __half h = __float2half_rn(src[r * 256 + kt * 32 + col]);
        *(__half*)(dst + tile_off(r, col >> 3) + (col & 7) * 2) = h;
    }
}

// ---------------------------------------------------------------------------
// Fused projection kernel v4: 512 threads (16 warps, 4x4 warp grid).
// Per CTA: 64 rows. Weights via cp.async from preconverted fp16 blocks.
// ---------------------------------------------------------------------------
#define FP_SMEM (229376 + 1024)

// smem map (from 1024-aligned base):
//  XT  : 0      .. 32KB   x tile, 8 chunks x [64][32] fp16
//  CT  : 32KB   .. 64KB   ctx tile
//  WB0 : 64KB   .. 80KB   weight stage 0 ([256][32] fp16)
//  WB1 : 80KB   .. 96KB   weight stage 1
//  SC  : 96KB   .. 160KB  scale [64][256] fp32, shifted cols
//  SH  : 160KB  .. 224KB  shift

__global__ void __launch_bounds__(512, 1)
fused_proj(const float* __restrict__ x, const float* __restrict__ ctx,
           float* __restrict__ outq, float* __restrict__ outk,
           float* __restrict__ outv)
{
    extern __shared__ uint8_t smraw[];
    const uint32_t base = (smem_u32(smraw) + 1023u) & ~1023u;
    const uint32_t XT  = base;
    const uint32_t CT  = base + 32768;
    const uint32_t WB0 = base + 65536;
    const uint32_t WB1 = base + 81920;
    const uint32_t SC  = base + 98304;
    const uint32_t SH  = base + 163840;

    const int tid = threadIdx.x, wid = tid >> 5, lane = tid & 31;
    const int m0 = blockIdx.x * 64;
    const int warp_m = (wid & 3) * 16;   // 4 warps down M (64)
    const int warp_n = (wid >> 2) * 64;  // 4 warps across N (256)

    // ---- Stage x & ctx tiles: 64 rows x 256 fp32 -> fp16 chunk-major ----
    {
        const float* xp = x   + (size_t)m0 * CDIM;
        const float* cp = ctx + (size_t)m0 * CDIM;
        #pragma unroll
        for (int i = 0; i < 4; i++) {
            const int unit = i * 512 + tid;       // 2048 units of 8 floats
            const int row = unit >> 5, u = unit & 31;
            const int kc = u >> 2, c = u & 3;
            const uint32_t so = (uint32_t)(kc * 4096) + tile_off(row, c);
            const float4* p = (const float4*)(xp + row * CDIM + u * 8);
            float4 f0 = p[0], f1 = p[1];
            uint4 v;
            v.x = packh2(f0.x, f0.y); v.y = packh2(f0.z, f0.w);
            v.z = packh2(f1.x, f1.y); v.w = packh2(f1.z, f1.w);
            asm volatile("st.shared.v4.b32 [%0], {%1,%2,%3,%4};" ::
                "r"(XT + so), "r"(v.x), "r"(v.y), "r"(v.z), "r"(v.w) : "memory");
            p = (const float4*)(cp + row * CDIM + u * 8);
            f0 = p[0]; f1 = p[1];
            v.x = packh2(f0.x, f0.y); v.y = packh2(f0.z, f0.w);
            v.z = packh2(f1.x, f1.y); v.w = packh2(f1.z, f1.w);
            asm volatile("st.shared.v4.b32 [%0], {%1,%2,%3,%4};" ::
                "r"(CT + so), "r"(v.x), "r"(v.y), "r"(v.z), "r"(v.w) : "memory");
        }
    }
    __syncthreads();

    // cp.async weight stage: 16KB block, 512 threads x 32B.
    auto ldw_async = [&](int mat, int kt, uint32_t buf) {
        const uint8_t* src = (const uint8_t*)g_wh
                           + ((size_t)(mat * 8 + kt) << 14) + tid * 32;
        const uint32_t d0 = buf + tid * 32;
        CP_ASYNC16(d0,      src);
        CP_ASYNC16(d0 + 16, src + 16);
        CP_COMMIT();
    };

    float d[8][4];
    auto do_gemm = [&](int mat, uint32_t at) {
        #pragma unroll
        for (int nt = 0; nt < 8; nt++)
            #pragma unroll
            for (int i = 0; i < 4; i++) d[nt][i] = 0.f;
        ldw_async(mat, 0, WB0);
        #pragma unroll 1
        for (int kt = 0; kt < 8; kt++) {
            CP_WAIT0();              // weight stage kt landed
            __syncthreads();         // visible to all; prior MMA certified done
            if (kt < 7) ldw_async(mat, kt + 1, (kt & 1) ? WB0 : WB1);
            const uint32_t wb = (kt & 1) ? WB1 : WB0;
            const uint32_t ac = at + kt * 4096;
            #pragma unroll
            for (int s = 0; s < 2; s++) {
                uint32_t a[4];
                const int R = warp_m + (lane & 15);
                const int c = s * 2 + (lane >> 4);
                LDSM_X4(a[0], a[1], a[2], a[3], ac + tile_off(R, c));
                #pragma unroll
                for (int np = 0; np < 4; np++) {
                    const int g = lane >> 3, lr = lane & 7;
                    const int Rn = warp_n + np * 16 + ((g >> 1) << 3) + lr;
                    const int cb = s * 2 + (g & 1);
                    uint32_t b[4];
                    LDSM_X4(b[0], b[1], b[2], b[3], wb + tile_off(Rn, cb));
                    MMA16816(d[np * 2 + 0], a, b[0], b[1]);
                    MMA16816(d[np * 2 + 1], a, b[2], b[3]);
                }
            }
        }
    };

    // shifted fp32 [64][256] smem accessors (write/read same-thread)
    auto smoff = [&](int row, int col) -> uint32_t {
        const int colp = (col + row * 8) & 255;
        return (uint32_t)(row * 1024 + colp * 4);
    };

    // ---- scale, shift (from ctx tile) -> smem ----
    const uint32_t Sm[2] = {SC, SH};
    #pragma unroll 1
    for (int mphase = 0; mphase < 2; mphase++) {
        do_gemm(mphase, CT);                 // mat 0=Wscale, 1=Wshift
        #pragma unroll
        for (int half = 0; half < 2; half++) {
            const int row = warp_m + (lane >> 2) + half * 8;
            #pragma unroll
            for (int nt = 0; nt < 8; nt++) {
                const int col = warp_n + nt * 8 + (lane & 3) * 2;
                asm volatile("st.shared.v2.b32 [%0], {%1,%2};" ::
                    "r"(Sm[mphase] + smoff(row, col)),
                    "r"(__float_as_uint(d[nt][half * 2 + 0])),
                    "r"(__float_as_uint(d[nt][half * 2 + 1])) : "memory");
            }
        }
        __syncthreads();
    }

    // ---- q, k, v (from x tile) with fused FiLM ----
    float* Outs[3] = {outq, outk, outv};
    #pragma unroll 1
    for (int mphase = 0; mphase < 3; mphase++) {
        do_gemm(2 + mphase, XT);             // mats 2=Wq, 3=Wk, 4=Wv
        float* outp = Outs[mphase];
        #pragma unroll
        for (int half = 0; half < 2; half++) {
            const int row = warp_m + (lane >> 2) + half * 8;
            const size_t rbase = (size_t)(m0 + row) * CDIM;
            #pragma unroll
            for (int nt = 0; nt < 8; nt++) {
                const int col = warp_n + nt * 8 + (lane & 3) * 2;
                uint32_t sx, sy, tx, ty;
                asm volatile("ld.shared.v2.b32 {%0,%1}, [%2];"
                    : "=r"(sx), "=r"(sy) : "r"(SC + smoff(row, col)));
                asm volatile("ld.shared.v2.b32 {%0,%1}, [%2];"
                    : "=r"(tx), "=r"(ty) : "r"(SH + smoff(row, col)));
                float2 v;
                v.x = fmaf(__uint_as_float(sx), d[nt][half * 2 + 0],
                           __uint_as_float(tx));
                v.y = fmaf(__uint_as_float(sy), d[nt][half * 2 + 1],
                           __uint_as_float(ty));
                *(float2*)(outp + rbase + col) = v;
            }
        }
        __syncthreads();
    }
}

// ---------------------------------------------------------------------------
// Out-projection GEMM (unchanged from R9): out = A @ Wout^T, K=256.
// ---------------------------------------------------------------------------
__global__ void __launch_bounds__(256)
gemm_h16(const float* __restrict__ A, float* __restrict__ out)
{
    constexpr int K = 256;
    __shared__ alignas(128) uint8_t sA[2][8192];
    __shared__ alignas(128) uint8_t sB[2][8192];

    const int tid  = threadIdx.x;
    const int wid  = tid >> 5;
    const int lane = tid & 31;
    const int m0 = blockIdx.y * 128;
    const int n0 = blockIdx.x * 128;

    const int warp_m = (wid & 3) * 32;
    const int warp_n = (wid >> 2) * 64;

    const uint32_t sa0 = smem_u32(&sA[0][0]);
    const uint32_t sa1 = smem_u32(&sA[1][0]);
    const uint32_t sb0 = smem_u32(&sB[0][0]);
    const uint32_t sb1 = smem_u32(&sB[1][0]);

    const int r0i = tid >> 2, c0i = tid & 3;
    const int r1i = (tid + 256) >> 2, c1i = tid & 3;
    const float* Ap = A + (size_t)m0 * K;

    float d[2][8][4];
    #pragma unroll
    for (int mt = 0; mt < 2; mt++)
        #pragma unroll
        for (int nt = 0; nt < 8; nt++)
            #pragma unroll
            for (int i = 0; i < 4; i++) d[mt][nt][i] = 0.f;

    uint4 pa[2];
    auto ldcvt = [&](int row, int c, int kt) -> uint4 {
        const float4* p = (const float4*)(Ap + (size_t)row * K + kt * 32 + c * 8);
        const float4 f0 = p[0], f1 = p[1];
        uint4 u;
        u.x = packh2(f0.x, f0.y); u.y = packh2(f0.z, f0.w);
        u.z = packh2(f1.x, f1.y); u.w = packh2(f1.z, f1.w);
        return u;
    };
    auto stsA = [&](uint32_t abuf) {
        asm volatile("st.shared.v4.b32 [%0], {%1,%2,%3,%4};" ::
            "r"(abuf + tile_off(r0i, c0i)), "r"(pa[0].x), "r"(pa[0].y), "r"(pa[0].z), "r"(pa[0].w) : "memory");
        asm volatile("st.shared.v4.b32 [%0], {%1,%2,%3,%4};" ::
            "r"(abuf + tile_off(r1i, c1i)), "r"(pa[1].x), "r"(pa[1].y), "r"(pa[1].z), "r"(pa[1].w) : "memory");
    };
    auto ldb_async = [&](int kt, uint32_t buf) {
        const uint8_t* src = (const uint8_t*)g_wh + ((size_t)(40 + kt) << 14)
                           + n0 * 64 + tid * 32;
        const uint32_t d0 = buf + tid * 32;
        CP_ASYNC16(d0,      src);
        CP_ASYNC16(d0 + 16, src + 16);
        CP_COMMIT();
    };

    ldb_async(0, sb0);
    pa[0] = ldcvt(r0i, c0i, 0); pa[1] = ldcvt(r1i, c1i, 0);
    stsA(sa0);
    __syncthreads();

    #pragma unroll 1
    for (int kt = 0; kt < 8; kt++) {
        if (kt < 7) { pa[0] = ldcvt(r0i, c0i, kt + 1); pa[1] = ldcvt(r1i, c1i, kt + 1); }
        CP_WAIT0();
        __syncthreads();
        if (kt < 7) ldb_async(kt + 1, (kt & 1) ? sb0 : sb1);
        const uint32_t abuf = (kt & 1) ? sa1 : sa0;
        const uint32_t bbuf = (kt & 1) ? sb1 : sb0;

        #pragma unroll
        for (int s = 0; s < 2; s++) {
            uint32_t a[2][4];
            #pragma unroll
            for (int mt = 0; mt < 2; mt++) {
                const int R = warp_m + mt * 16 + (lane & 15);
                const int c = s * 2 + (lane >> 4);
                LDSM_X4(a[mt][0], a[mt][1], a[mt][2], a[mt][3],
                        abuf + tile_off(R, c));
            }
            #pragma unroll
            for (int np = 0; np < 4; np++) {
                const int g = lane >> 3, lr = lane & 7;
                const int Rn = warp_n + np * 16 + ((g >> 1) << 3) + lr;
                const int c = s * 2 + (g & 1);
                uint32_t b[4];
                LDSM_X4(b[0], b[1], b[2], b[3], bbuf + tile_off(Rn, c));
                #pragma unroll
                for (int mt = 0; mt < 2; mt++) {
                    MMA16816(d[mt][np * 2 + 0], a[mt], b[0], b[1]);
                    MMA16816(d[mt][np * 2 + 1], a[mt], b[2], b[3]);
                }
            }
        }
        __syncthreads();
        if (kt < 7) stsA((kt & 1) ? sa0 : sa1);
    }

    #pragma unroll
    for (int mt = 0; mt < 2; mt++) {
        #pragma unroll
        for (int half = 0; half < 2; half++) {
            const int row = m0 + warp_m + mt * 16 + (lane >> 2) + half * 8;
            const size_t rbase = (size_t)row * CDIM;
            #pragma unroll
            for (int nt = 0; nt < 8; nt++) {
                const int col = n0 + warp_n + nt * 8 + (lane & 3) * 2;
                float2 v;
                v.x = d[mt][nt][half * 2 + 0];
                v.y = d[mt][nt][half * 2 + 1];
                *(float2*)(out + rbase + col) = v;
            }
        }
    }
}

// ---------------------------------------------------------------------------
// Tensor-core attention (unchanged from R8).
// ---------------------------------------------------------------------------
#define AT_SMEM (57344 + 1024)

__global__ void __launch_bounds__(128)
attn_mma(const float* __restrict__ Qg, const float* __restrict__ Kg,
         const float* __restrict__ Vg, float* __restrict__ O)
{
    extern __shared__ uint8_t smraw[];
    const uint32_t base = (smem_u32(smraw) + 1023u) & ~1023u;
    const uint32_t SQ = base;
    const uint32_t SK = base + 8192;
    const uint32_t SVT = base + 16384;
    const uint32_t SP = base + 24576;

    const int tid = threadIdx.x, wid = tid >> 5, lane = tid & 31;
    const int bh = blockIdx.x;
    const size_t r0 = (size_t)(bh >> 3) * 128;
    const int c0 = (bh & 7) * 32;
    const int warp_m = wid * 32;

    {
        const int part = tid & 3;
        #pragma unroll
        for (int pass = 0; pass < 4; pass++) {
            const int row = (tid >> 2) + pass * 32;
            const float4* qp = (const float4*)(Qg + (r0 + row) * CDIM + c0 + part * 8);
            const float4* kp = (const float4*)(Kg + (r0 + row) * CDIM + c0 + part * 8);
            float4 f0 = qp[0], f1 = qp[1];
            uint4 v;
            v.x = packh2(f0.x, f0.y); v.y = packh2(f0.z, f0.w);
            v.z = packh2(f1.x, f1.y); v.w = packh2(f1.z, f1.w);
            asm volatile("st.shared.v4.b32 [%0], {%1,%2,%3,%4};" ::
                "r"(SQ + tile_off(row, part)), "r"(v.x), "r"(v.y), "r"(v.z), "r"(v.w) : "memory");
            f0 = kp[0]; f1 = kp[1];
            v.x = packh2(f0.x, f0.y); v.y = packh2(f0.z, f0.w);
            v.z = packh2(f1.x, f1.y); v.w = packh2(f1.z, f1.w);
            asm volatile("st.shared.v4.b32 [%0], {%1,%2,%3,%4};" ::
                "r"(SK + tile_off(row, part)), "r"(v.x), "r"(v.y), "r"(v.z), "r"(v.w) : "memory");
        }
        #pragma unroll
        for (int pass = 0; pass < 4; pass++) {
            const int j = (tid >> 2) + pass * 32;
            const int e0 = part * 8;
            const float4* vp = (const float4*)(Vg + (r0 + j) * CDIM + c0 + e0);
            const float4 f0 = vp[0], f1 = vp[1];
            const float fv[8] = {f0.x, f0.y, f0.z, f0.w, f1.x, f1.y, f1.z, f1.w};
            const uint32_t cb = SVT + (j >> 5) * 2048;
            const int jc = j & 31;
            #pragma unroll
            for (int i = 0; i < 8; i++) {
                const __half h = __float2half_rn(fv[i]);
                const uint16_t hb = *(const uint16_t*)&h;
                asm volatile("st.shared.b16 [%0], %1;" ::
                    "r"(cb + tile_off(e0 + i, jc >> 3) + (jc & 7) * 2), "h"(hb) : "memory");
            }
        }
    }
    __syncthreads();

    float d[2][16][4];
    #pragma unroll
    for (int mt = 0; mt < 2; mt++)
        #pragma unroll
        for (int nt = 0; nt < 16; nt++)
            #pragma unroll
            for (int i = 0; i < 4; i++) d[mt][nt][i] = 0.f;

    #pragma unroll
    for (int s = 0; s < 2; s++) {
        uint32_t a[2][4];
        #pragma unroll
        for (int mt = 0; mt < 2; mt++) {
            const int R = warp_m + mt * 16 + (lane & 15);
            const int c = s * 2 + (lane >> 4);
            LDSM_X4(a[mt][0], a[mt][1], a[mt][2], a[mt][3], SQ + tile_off(R, c));
        }
        #pragma unroll
        for (int np = 0; np < 8; np++) {
            const int g = lane >> 3, lr = lane & 7;
            const int Rn = np * 16 + ((g >> 1) << 3) + lr;
            const int c = s * 2 + (g & 1);
            uint32_t b[4];
            LDSM_X4(b[0], b[1], b[2], b[3], SK + tile_off(Rn, c));
            #pragma unroll
            for (int mt = 0; mt < 2; mt++) {
                MMA16816(d[mt][np * 2 + 0], a[mt], b[0], b[1]);
                MMA16816(d[mt][np * 2 + 1], a[mt], b[2], b[3]);
            }
        }
    }

    const float sc = 0.17677669529663687f;
    float inv[2][2];
    #pragma unroll
    for (int mt = 0; mt < 2; mt++) {
        #pragma unroll
        for (int half = 0; half < 2; half++) {
            float mx = -1e30f;
            #pragma unroll
            for (int nt = 0; nt < 16; nt++) {
                mx = fmaxf(mx, fmaxf(d[mt][nt][half * 2], d[mt][nt][half * 2 + 1]));
            }
            mx = fmaxf(mx, __shfl_xor_sync(0xffffffffu, mx, 1));
            mx = fmaxf(mx, __shfl_xor_sync(0xffffffffu, mx, 2));
            const float mxs = mx * sc;
            float sum = 0.f;
            const int row = warp_m + mt * 16 + (lane >> 2) + half * 8;
            #pragma unroll
            for (int nt = 0; nt < 16; nt++) {
                const float p0 = __expf(fmaf(d[mt][nt][half * 2 + 0], sc, -mxs));
                const float p1 = __expf(fmaf(d[mt][nt][half * 2 + 1], sc, -mxs));
                sum += p0 + p1;
                const int jc = (nt & 3) * 8 + (lane & 3) * 2;
                asm volatile("st.shared.b32 [%0], %1;" ::
                    "r"(SP + (nt >> 2) * 8192 + tile_off(row, jc >> 3) + (jc & 7) * 2),
                    "r"(packh2(p0, p1)) : "memory");
            }
            sum += __shfl_xor_sync(0xffffffffu, sum, 1);
            sum += __shfl_xor_sync(0xffffffffu, sum, 2);
            inv[mt][half] = 1.f / sum;
        }
    }
    __syncwarp();

    float o[2][4][4];
    #pragma unroll
    for (int mt = 0; mt < 2; mt++)
        #pragma unroll
        for (int nt = 0; nt < 4; nt++)
            #pragma unroll
            for (int i = 0; i < 4; i++) o[mt][nt][i] = 0.f;

    #pragma unroll
    for (int ck = 0; ck < 4; ck++) {
        const uint32_t pb = SP + ck * 8192;
        const uint32_t vb = SVT + ck * 2048;
        #pragma unroll
        for (int s = 0; s < 2; s++) {
            uint32_t a[2][4];
            #pragma unroll
            for (int mt = 0; mt < 2; mt++) {
                const int R = warp_m + mt * 16 + (lane & 15);
                const int c = s * 2 + (lane >> 4);
                LDSM_X4(a[mt][0], a[mt][1], a[mt][2], a[mt][3], pb + tile_off(R, c));
            }
            #pragma unroll
            for (int np = 0; np < 2; np++) {
                const int g = lane >> 3, lr = lane & 7;
                const int Rn = np * 16 + ((g >> 1) << 3) + lr;
                const int c = s * 2 + (g & 1);
                uint32_t b[4];
                LDSM_X4(b[0], b[1], b[2], b[3], vb + tile_off(Rn, c));
                #pragma unroll
                for (int mt = 0; mt < 2; mt++) {
                    MMA16816(o[mt][np * 2 + 0], a[mt], b[0], b[1]);
                    MMA16816(o[mt][np * 2 + 1], a[mt], b[2], b[3]);
                }
            }
        }
    }

    #pragma unroll
    for (int mt = 0; mt < 2; mt++) {
        #pragma unroll
        for (int half = 0; half < 2; half++) {
            const int row = warp_m + mt * 16 + (lane >> 2) + half * 8;
            const float iv = inv[mt][half];
            const size_t rbase = (r0 + row) * CDIM + c0;
            #pragma unroll
            for (int nt = 0; nt < 4; nt++) {
                const int col = nt * 8 + (lane & 3) * 2;
                float2 v;
                v.x = o[mt][nt][half * 2 + 0] * iv;
                v.y = o[mt][nt][half * 2 + 1] * iv;
                *(float2*)(O + rbase + col) = v;
            }
        }
    }
}

// ---------------------------------------------------------------------------
// Launch
// ---------------------------------------------------------------------------
extern "C" void kernel_launch(void* const* d_in, const int* in_sizes, int n_in,
                              void* d_out, int out_size)
{
    const float* x      = (const float*)d_in[0];
    const float* ctx    = (const float*)d_in[1];
    const float* Wq     = (const float*)d_in[2];
    const float* Wkv    = (const float*)d_in[3];
    const float* Wout   = (const float*)d_in[4];
    const float* Wscale = (const float*)d_in[5];
    const float* Wshift = (const float*)d_in[6];
    float* out = (float*)d_out;

    float *gq, *gk, *gv, *ga;
    cudaGetSymbolAddress((void**)&gq, g_q);
    cudaGetSymbolAddress((void**)&gk, g_k);
    cudaGetSymbolAddress((void**)&gv, g_v);
    cudaGetSymbolAddress((void**)&ga, g_attn);

    cudaFuncSetAttribute(fused_proj,
                         cudaFuncAttributeMaxDynamicSharedMemorySize, FP_SMEM);
    cudaFuncSetAttribute(attn_mma,
                         cudaFuncAttributeMaxDynamicSharedMemorySize, AT_SMEM);

    // one-time-per-call weight preconversion (fp16, swizzled chunk layout)
    wcvt<<<48, 256>>>(Wq, Wkv, Wscale, Wshift, Wout);

    // Fused scale/shift/q/k/v projections with FiLM (512 threads)
    fused_proj<<<MROWS / 64, 512, FP_SMEM>>>(x, ctx, gq, gk, gv);

    // attention: 1024 batches x 8 heads, tensor-core
    attn_mma<<<8192, 128, AT_SMEM>>>(gq, gk, gv, ga);

    // output projection straight into d_out
    gemm_h16<<<dim3(2, 1024), 256>>>(ga, out);
}

// round 11
// speedup vs baseline: 2.2809x; 1.0637x over previous
#include <cuda_runtime.h>
#include <cuda_fp16.h>
#include <cstdint>
#include <math.h>

// Fixed shapes: B=8, C=256, H=128, W=128, heads=8, e=32
#define MROWS 131072
#define CDIM  256
#define NELEM (MROWS * CDIM)

// Scratch (allocation-free rule: __device__ globals)
// Intermediates are fp16: producers apply the same __float2half_rn the
// consumers used before, so the MMA inputs are bit-identical.
__device__ __align__(16) __half g_q[NELEM];
__device__ __align__(16) __half g_k[NELEM];
__device__ __align__(16) __half g_v[NELEM];
__device__ __align__(16) __half g_attn[NELEM];
// Preconverted fp16 weights, swizzled chunk-major:
// 6 mats x 8 ksteps x [256 rows][32 cols] fp16 (16KB blocks)
// mats: 0=Wscale 1=Wshift 2=Wq 3=Wk 4=Wv 5=Wout
__device__ __align__(16) uint16_t g_wh[6 * 8 * 8192];

// ---------------------------------------------------------------------------
// PTX helpers (sm_80-level: ldmatrix + mma.sync + cp.async)
// ---------------------------------------------------------------------------
__device__ __forceinline__ uint32_t smem_u32(const void* p) {
    uint32_t a;
    asm("{ .reg .u64 t; cvta.to.shared.u64 t, %1; cvt.u32.u64 %0, t; }"
        : "=r"(a) : "l"(p));
    return a;
}

#define LDSM_X4(r0, r1, r2, r3, addr)                                         \
    asm volatile("ldmatrix.sync.aligned.m8n8.x4.shared.b16 {%0,%1,%2,%3}, [%4];" \
                 : "=r"(r0), "=r"(r1), "=r"(r2), "=r"(r3) : "r"(addr))

#define MMA16816(d, a, b0, b1)                                                \
    asm volatile("mma.sync.aligned.m16n8k16.row.col.f32.f16.f16.f32 "         \
                 "{%0,%1,%2,%3}, {%4,%5,%6,%7}, {%8,%9}, {%0,%1,%2,%3};"      \
                 : "+f"((d)[0]), "+f"((d)[1]), "+f"((d)[2]), "+f"((d)[3])     \
                 : "r"((a)[0]), "r"((a)[1]), "r"((a)[2]), "r"((a)[3]),        \
                   "r"(b0), "r"(b1))

#define CP_ASYNC16(dst, src)                                                  \
    asm volatile("cp.async.cg.shared.global [%0], [%1], 16;" ::               \
                 "r"(dst), "l"(src) : "memory")
#define CP_COMMIT()  asm volatile("cp.async.commit_group;" ::: "memory")
#define CP_WAIT0()   asm volatile("cp.async.wait_group 0;" ::: "memory")

__device__ __forceinline__ uint32_t packh2(float x, float y) {
    __half2 h = __floats2half2_rn(x, y);
    return *(uint32_t*)&h;
}

// Swizzled byte offset for chunk (row, c) of a [rows][32]-fp16 tile
// (pair-rows of 128B; c = 16B chunk index 0..3). Works for rows<=256.
__device__ __forceinline__ uint32_t tile_off(int row, int c) {
    const int pr = row >> 1;
    const int ch = ((row & 1) << 2) | c;
    return (uint32_t)(pr * 128 + ((ch ^ (pr & 7)) << 4));
}

// ---------------------------------------------------------------------------
// Weight preconversion: fp32 -> fp16 in swizzled chunk-major layout.
// ---------------------------------------------------------------------------
__global__ void __launch_bounds__(256)
wcvt(const float* __restrict__ Wq, const float* __restrict__ Wkv,
     const float* __restrict__ Wscale, const float* __restrict__ Wshift,
     const float* __restrict__ Wout)
{
    const int blk = blockIdx.x;
    const int mat = blk >> 3, kt = blk & 7;
    const float* srcs[6] = {Wscale, Wshift, Wq, Wkv, Wkv + 65536, Wout};
    const float* src = srcs[mat];
    uint8_t* dst = (uint8_t*)g_wh + (size_t)blk * 16384;
    for (int i = threadIdx.x; i < 8192; i += 256) {
        const int r = i >> 5, col = i & 31;
        const __half h = __float2half_rn(src[r * 256 + kt * 32 + col]);
        *(__half*)(dst + tile_off(r, col >> 3) + (col & 7) * 2) = h;
    }
}

// ---------------------------------------------------------------------------
// Fused projection kernel v5: 512 threads (16 warps, 4x4 warp grid).
// Per CTA: 64 rows. Weights via cp.async; q/k/v written as fp16.
// ---------------------------------------------------------------------------
#define FP_SMEM (229376 + 1024)

__global__ void __launch_bounds__(512, 1)
fused_proj(const float* __restrict__ x, const float* __restrict__ ctx,
           __half* __restrict__ outq, __half* __restrict__ outk,
           __half* __restrict__ outv)
{
    extern __shared__ uint8_t smraw[];
    const uint32_t base = (smem_u32(smraw) + 1023u) & ~1023u;
    const uint32_t XT  = base;
    const uint32_t CT  = base + 32768;
    const uint32_t WB0 = base + 65536;
    const uint32_t WB1 = base + 81920;
    const uint32_t SC  = base + 98304;
    const uint32_t SH  = base + 163840;

    const int tid = threadIdx.x, wid = tid >> 5, lane = tid & 31;
    const int m0 = blockIdx.x * 64;
    const int warp_m = (wid & 3) * 16;   // 4 warps down M (64)
    const int warp_n = (wid >> 2) * 64;  // 4 warps across N (256)

    // ---- Stage x & ctx tiles: 64 rows x 256 fp32 -> fp16 chunk-major ----
    {
        const float* xp = x   + (size_t)m0 * CDIM;
        const float* cp = ctx + (size_t)m0 * CDIM;
        #pragma unroll
        for (int i = 0; i < 4; i++) {
            const int unit = i * 512 + tid;       // 2048 units of 8 floats
            const int row = unit >> 5, u = unit & 31;
            const int kc = u >> 2, c = u & 3;
            const uint32_t so = (uint32_t)(kc * 4096) + tile_off(row, c);
            const float4* p = (const float4*)(xp + row * CDIM + u * 8);
            float4 f0 = p[0], f1 = p[1];
            uint4 v;
            v.x = packh2(f0.x, f0.y); v.y = packh2(f0.z, f0.w);
            v.z = packh2(f1.x, f1.y); v.w = packh2(f1.z, f1.w);
            asm volatile("st.shared.v4.b32 [%0], {%1,%2,%3,%4};" ::
                "r"(XT + so), "r"(v.x), "r"(v.y), "r"(v.z), "r"(v.w) : "memory");
            p = (const float4*)(cp + row * CDIM + u * 8);
            f0 = p[0]; f1 = p[1];
            v.x = packh2(f0.x, f0.y); v.y = packh2(f0.z, f0.w);
            v.z = packh2(f1.x, f1.y); v.w = packh2(f1.z, f1.w);
            asm volatile("st.shared.v4.b32 [%0], {%1,%2,%3,%4};" ::
                "r"(CT + so), "r"(v.x), "r"(v.y), "r"(v.z), "r"(v.w) : "memory");
        }
    }
    __syncthreads();

    // cp.async weight stage: 16KB block, 512 threads x 32B.
    auto ldw_async = [&](int mat, int kt, uint32_t buf) {
        const uint8_t* src = (const uint8_t*)g_wh
                           + ((size_t)(mat * 8 + kt) << 14) + tid * 32;
        const uint32_t d0 = buf + tid * 32;
        CP_ASYNC16(d0,      src);
        CP_ASYNC16(d0 + 16, src + 16);
        CP_COMMIT();
    };

    float d[8][4];
    auto do_gemm = [&](int mat, uint32_t at) {
        #pragma unroll
        for (int nt = 0; nt < 8; nt++)
            #pragma unroll
            for (int i = 0; i < 4; i++) d[nt][i] = 0.f;
        ldw_async(mat, 0, WB0);
        #pragma unroll 1
        for (int kt = 0; kt < 8; kt++) {
            CP_WAIT0();
            __syncthreads();
            if (kt < 7) ldw_async(mat, kt + 1, (kt & 1) ? WB0 : WB1);
            const uint32_t wb = (kt & 1) ? WB1 : WB0;
            const uint32_t ac = at + kt * 4096;
            #pragma unroll
            for (int s = 0; s < 2; s++) {
                uint32_t a[4];
                const int R = warp_m + (lane & 15);
                const int c = s * 2 + (lane >> 4);
                LDSM_X4(a[0], a[1], a[2], a[3], ac + tile_off(R, c));
                #pragma unroll
                for (int np = 0; np < 4; np++) {
                    const int g = lane >> 3, lr = lane & 7;
                    const int Rn = warp_n + np * 16 + ((g >> 1) << 3) + lr;
                    const int cb = s * 2 + (g & 1);
                    uint32_t b[4];
                    LDSM_X4(b[0], b[1], b[2], b[3], wb + tile_off(Rn, cb));
                    MMA16816(d[np * 2 + 0], a, b[0], b[1]);
                    MMA16816(d[np * 2 + 1], a, b[2], b[3]);
                }
            }
        }
    };

    // shifted fp32 [64][256] smem accessors (write/read same-thread)
    auto smoff = [&](int row, int col) -> uint32_t {
        const int colp = (col + row * 8) & 255;
        return (uint32_t)(row * 1024 + colp * 4);
    };

    // ---- scale, shift (from ctx tile) -> smem (fp32, bit-identical) ----
    const uint32_t Sm[2] = {SC, SH};
    #pragma unroll 1
    for (int mphase = 0; mphase < 2; mphase++) {
        do_gemm(mphase, CT);                 // mat 0=Wscale, 1=Wshift
        #pragma unroll
        for (int half = 0; half < 2; half++) {
            const int row = warp_m + (lane >> 2) + half * 8;
            #pragma unroll
            for (int nt = 0; nt < 8; nt++) {
                const int col = warp_n + nt * 8 + (lane & 3) * 2;
                asm volatile("st.shared.v2.b32 [%0], {%1,%2};" ::
                    "r"(Sm[mphase] + smoff(row, col)),
                    "r"(__float_as_uint(d[nt][half * 2 + 0])),
                    "r"(__float_as_uint(d[nt][half * 2 + 1])) : "memory");
            }
        }
        __syncthreads();
    }

    // ---- q, k, v (from x tile) with fused FiLM; fp16 stores ----
    __half* Outs[3] = {outq, outk, outv};
    #pragma unroll 1
    for (int mphase = 0; mphase < 3; mphase++) {
        do_gemm(2 + mphase, XT);             // mats 2=Wq, 3=Wk, 4=Wv
        __half* outp = Outs[mphase];
        #pragma unroll
        for (int half = 0; half < 2; half++) {
            const int row = warp_m + (lane >> 2) + half * 8;
            const size_t rbase = (size_t)(m0 + row) * CDIM;
            #pragma unroll
            for (int nt = 0; nt < 8; nt++) {
                const int col = warp_n + nt * 8 + (lane & 3) * 2;
                uint32_t sx, sy, tx, ty;
                asm volatile("ld.shared.v2.b32 {%0,%1}, [%2];"
                    : "=r"(sx), "=r"(sy) : "r"(SC + smoff(row, col)));
                asm volatile("ld.shared.v2.b32 {%0,%1}, [%2];"
                    : "=r"(tx), "=r"(ty) : "r"(SH + smoff(row, col)));
                const float vx = fmaf(__uint_as_float(sx), d[nt][half * 2 + 0],
                                      __uint_as_float(tx));
                const float vy = fmaf(__uint_as_float(sy), d[nt][half * 2 + 1],
                                      __uint_as_float(ty));
                *(uint32_t*)(outp + rbase + col) = packh2(vx, vy);
            }
        }
        __syncthreads();
    }
}

// ---------------------------------------------------------------------------
// Out-projection GEMM v3: out = A @ Wout^T, K=256. A is fp16 in gmem:
// both A and B stages are pure cp.async byte-copies (one commit group/step).
// ---------------------------------------------------------------------------
__global__ void __launch_bounds__(256)
gemm_h16(const __half* __restrict__ A, float* __restrict__ out)
{
    __shared__ alignas(128) uint8_t sA[2][8192];
    __shared__ alignas(128) uint8_t sB[2][8192];

    const int tid  = threadIdx.x;
    const int wid  = tid >> 5;
    const int lane = tid & 31;
    const int m0 = blockIdx.y * 128;
    const int n0 = blockIdx.x * 128;

    const int warp_m = (wid & 3) * 32;
    const int warp_n = (wid >> 2) * 64;

    const uint32_t sa0 = smem_u32(&sA[0][0]);
    const uint32_t sa1 = smem_u32(&sA[1][0]);
    const uint32_t sb0 = smem_u32(&sB[0][0]);
    const uint32_t sb1 = smem_u32(&sB[1][0]);

    float d[2][8][4];
    #pragma unroll
    for (int mt = 0; mt < 2; mt++)
        #pragma unroll
        for (int nt = 0; nt < 8; nt++)
            #pragma unroll
            for (int i = 0; i < 4; i++) d[mt][nt][i] = 0.f;

    // A stage: 8KB = [128 rows][32 cols] fp16 of rows [m0, m0+128), kstep kt.
    auto ldab_async = [&](int kt, uint32_t abuf, uint32_t bbuf) {
        #pragma unroll
        for (int u = 0; u < 2; u++) {
            const int idx = tid + u * 256;         // 512 units of 16B
            const int row = idx >> 2, c = idx & 3;
            const __half* src = A + (size_t)(m0 + row) * CDIM + kt * 32 + c * 8;
            CP_ASYNC16(abuf + tile_off(row, c), src);
        }
        const uint8_t* bsrc = (const uint8_t*)g_wh + ((size_t)(40 + kt) << 14)
                            + n0 * 64 + tid * 32;
        const uint32_t d0 = bbuf + tid * 32;
        CP_ASYNC16(d0,      bsrc);
        CP_ASYNC16(d0 + 16, bsrc + 16);
        CP_COMMIT();
    };

    ldab_async(0, sa0, sb0);

    #pragma unroll 1
    for (int kt = 0; kt < 8; kt++) {
        CP_WAIT0();
        __syncthreads();
        if (kt < 7) ldab_async(kt + 1, (kt & 1) ? sa0 : sa1, (kt & 1) ? sb0 : sb1);
        const uint32_t abuf = (kt & 1) ? sa1 : sa0;
        const uint32_t bbuf = (kt & 1) ? sb1 : sb0;

        #pragma unroll
        for (int s = 0; s < 2; s++) {
            uint32_t a[2][4];
            #pragma unroll
            for (int mt = 0; mt < 2; mt++) {
                const int R = warp_m + mt * 16 + (lane & 15);
                const int c = s * 2 + (lane >> 4);
                LDSM_X4(a[mt][0], a[mt][1], a[mt][2], a[mt][3],
                        abuf + tile_off(R, c));
            }
            #pragma unroll
            for (int np = 0; np < 4; np++) {
                const int g = lane >> 3, lr = lane & 7;
                const int Rn = warp_n + np * 16 + ((g >> 1) << 3) + lr;
                const int c = s * 2 + (g & 1);
                uint32_t b[4];
                LDSM_X4(b[0], b[1], b[2], b[3], bbuf + tile_off(Rn, c));
                #pragma unroll
                for (int mt = 0; mt < 2; mt++) {
                    MMA16816(d[mt][np * 2 + 0], a[mt], b[0], b[1]);
                    MMA16816(d[mt][np * 2 + 1], a[mt], b[2], b[3]);
                }
            }
        }
    }

    #pragma unroll
    for (int mt = 0; mt < 2; mt++) {
        #pragma unroll
        for (int half = 0; half < 2; half++) {
            const int row = m0 + warp_m + mt * 16 + (lane >> 2) + half * 8;
            const size_t rbase = (size_t)row * CDIM;
            #pragma unroll
            for (int nt = 0; nt < 8; nt++) {
                const int col = n0 + warp_n + nt * 8 + (lane & 3) * 2;
                float2 v;
                v.x = d[mt][nt][half * 2 + 0];
                v.y = d[mt][nt][half * 2 + 1];
                *(float2*)(out + rbase + col) = v;
            }
        }
    }
}

// ---------------------------------------------------------------------------
// Tensor-core attention v2: fp16 q/k/v in, fp16 O out (same rounding points
// as before -> bit-identical). One CTA (4 warps) per (batch, head).
// ---------------------------------------------------------------------------
#define AT_SMEM (57344 + 1024)

__global__ void __launch_bounds__(128)
attn_mma(const __half* __restrict__ Qg, const __half* __restrict__ Kg,
         const __half* __restrict__ Vg, __half* __restrict__ O)
{
    extern __shared__ uint8_t smraw[];
    const uint32_t base = (smem_u32(smraw) + 1023u) & ~1023u;
    const uint32_t SQ = base;
    const uint32_t SK = base + 8192;
    const uint32_t SVT = base + 16384;   // 4 chunks x 2KB, [32 e][32 j] each
    const uint32_t SP = base + 24576;    // 4 chunks x 8KB, [128 m][32 j] each

    const int tid = threadIdx.x, wid = tid >> 5, lane = tid & 31;
    const int bh = blockIdx.x;
    const size_t r0 = (size_t)(bh >> 3) * 128;
    const int c0 = (bh & 7) * 32;
    const int warp_m = wid * 32;

    // ---- Stage Q, K (straight fp16 copies) and V transposed ----
    {
        const int part = tid & 3;             // 16B chunk within 32-col row
        #pragma unroll
        for (int pass = 0; pass < 4; pass++) {
            const int row = (tid >> 2) + pass * 32;
            const uint4 qv = *(const uint4*)(Qg + (r0 + row) * CDIM + c0 + part * 8);
            asm volatile("st.shared.v4.b32 [%0], {%1,%2,%3,%4};" ::
                "r"(SQ + tile_off(row, part)), "r"(qv.x), "r"(qv.y), "r"(qv.z), "r"(qv.w) : "memory");
            const uint4 kv = *(const uint4*)(Kg + (r0 + row) * CDIM + c0 + part * 8);
            asm volatile("st.shared.v4.b32 [%0], {%1,%2,%3,%4};" ::
                "r"(SK + tile_off(row, part)), "r"(kv.x), "r"(kv.y), "r"(kv.z), "r"(kv.w) : "memory");
        }
        #pragma unroll
        for (int pass = 0; pass < 4; pass++) {
            const int j = (tid >> 2) + pass * 32;
            const int e0 = part * 8;
            const uint4 vv = *(const uint4*)(Vg + (r0 + j) * CDIM + c0 + e0);
            const uint16_t* hw = (const uint16_t*)&vv;
            const uint32_t cb = SVT + (j >> 5) * 2048;
            const int jc = j & 31;
            #pragma unroll
            for (int i = 0; i < 8; i++) {
                asm volatile("st.shared.b16 [%0], %1;" ::
                    "r"(cb + tile_off(e0 + i, jc >> 3) + (jc & 7) * 2), "h"(hw[i]) : "memory");
            }
        }
    }
    __syncthreads();

    float d[2][16][4];
    #pragma unroll
    for (int mt = 0; mt < 2; mt++)
        #pragma unroll
        for (int nt = 0; nt < 16; nt++)
            #pragma unroll
            for (int i = 0; i < 4; i++) d[mt][nt][i] = 0.f;

    #pragma unroll
    for (int s = 0; s < 2; s++) {
        uint32_t a[2][4];
        #pragma unroll
        for (int mt = 0; mt < 2; mt++) {
            const int R = warp_m + mt * 16 + (lane & 15);
            const int c = s * 2 + (lane >> 4);
            LDSM_X4(a[mt][0], a[mt][1], a[mt][2], a[mt][3], SQ + tile_off(R, c));
        }
        #pragma unroll
        for (int np = 0; np < 8; np++) {
            const int g = lane >> 3, lr = lane & 7;
            const int Rn = np * 16 + ((g >> 1) << 3) + lr;
            const int c = s * 2 + (g & 1);
            uint32_t b[4];
            LDSM_X4(b[0], b[1], b[2], b[3], SK + tile_off(Rn, c));
            #pragma unroll
            for (int mt = 0; mt < 2; mt++) {
                MMA16816(d[mt][np * 2 + 0], a[mt], b[0], b[1]);
                MMA16816(d[mt][np * 2 + 1], a[mt], b[2], b[3]);
            }
        }
    }

    const float sc = 0.17677669529663687f;
    float inv[2][2];
    #pragma unroll
    for (int mt = 0; mt < 2; mt++) {
        #pragma unroll
        for (int half = 0; half < 2; half++) {
            float mx = -1e30f;
            #pragma unroll
            for (int nt = 0; nt < 16; nt++) {
                mx = fmaxf(mx, fmaxf(d[mt][nt][half * 2], d[mt][nt][half * 2 + 1]));
            }
            mx = fmaxf(mx, __shfl_xor_sync(0xffffffffu, mx, 1));
            mx = fmaxf(mx, __shfl_xor_sync(0xffffffffu, mx, 2));
            const float mxs = mx * sc;
            float sum = 0.f;
            const int row = warp_m + mt * 16 + (lane >> 2) + half * 8;
            #pragma unroll
            for (int nt = 0; nt < 16; nt++) {
                const float p0 = __expf(fmaf(d[mt][nt][half * 2 + 0], sc, -mxs));
                const float p1 = __expf(fmaf(d[mt][nt][half * 2 + 1], sc, -mxs));
                sum += p0 + p1;
                const int jc = (nt & 3) * 8 + (lane & 3) * 2;
                asm volatile("st.shared.b32 [%0], %1;" ::
                    "r"(SP + (nt >> 2) * 8192 + tile_off(row, jc >> 3) + (jc & 7) * 2),
                    "r"(packh2(p0, p1)) : "memory");
            }
            sum += __shfl_xor_sync(0xffffffffu, sum, 1);
            sum += __shfl_xor_sync(0xffffffffu, sum, 2);
            inv[mt][half] = 1.f / sum;
        }
    }
    __syncwarp();

    float o[2][4][4];
    #pragma unroll
    for (int mt = 0; mt < 2; mt++)
        #pragma unroll
        for (int nt = 0; nt < 4; nt++)
            #pragma unroll
            for (int i = 0; i < 4; i++) o[mt][nt][i] = 0.f;

    #pragma unroll
    for (int ck = 0; ck < 4; ck++) {
        const uint32_t pb = SP + ck * 8192;
        const uint32_t vb = SVT + ck * 2048;
        #pragma unroll
        for (int s = 0; s < 2; s++) {
            uint32_t a[2][4];
            #pragma unroll
            for (int mt = 0; mt < 2; mt++) {
                const int R = warp_m + mt * 16 + (lane & 15);
                const int c = s * 2 + (lane >> 4);
                LDSM_X4(a[mt][0], a[mt][1], a[mt][2], a[mt][3], pb + tile_off(R, c));
            }
            #pragma unroll
            for (int np = 0; np < 2; np++) {
                const int g = lane >> 3, lr = lane & 7;
                const int Rn = np * 16 + ((g >> 1) << 3) + lr;
                const int c = s * 2 + (g & 1);
                uint32_t b[4];
                LDSM_X4(b[0], b[1], b[2], b[3], vb + tile_off(Rn, c));
                #pragma unroll
                for (int mt = 0; mt < 2; mt++) {
                    MMA16816(o[mt][np * 2 + 0], a[mt], b[0], b[1]);
                    MMA16816(o[mt][np * 2 + 1], a[mt], b[2], b[3]);
                }
            }
        }
    }

    // ---- Epilogue: normalize, round to fp16 (same point gemm_h16 rounded
    // before), store packed ----
    #pragma unroll
    for (int mt = 0; mt < 2; mt++) {
        #pragma unroll
        for (int half = 0; half < 2; half++) {
            const int row = warp_m + mt * 16 + (lane >> 2) + half * 8;
            const float iv = inv[mt][half];
            const size_t rbase = (r0 + row) * CDIM + c0;
            #pragma unroll
            for (int nt = 0; nt < 4; nt++) {
                const int col = nt * 8 + (lane & 3) * 2;
                *(uint32_t*)(O + rbase + col) =
                    packh2(o[mt][nt][half * 2 + 0] * iv,
                           o[mt][nt][half * 2 + 1] * iv);
            }
        }
    }
}

// ---------------------------------------------------------------------------
// Launch
// ---------------------------------------------------------------------------
extern "C" void kernel_launch(void* const* d_in, const int* in_sizes, int n_in,
                              void* d_out, int out_size)
{
    const float* x      = (const float*)d_in[0];
    const float* ctx    = (const float*)d_in[1];
    const float* Wq     = (const float*)d_in[2];
    const float* Wkv    = (const float*)d_in[3];
    const float* Wout   = (const float*)d_in[4];
    const float* Wscale = (const float*)d_in[5];
    const float* Wshift = (const float*)d_in[6];
    float* out = (float*)d_out;

    __half *gq, *gk, *gv, *ga;
    cudaGetSymbolAddress((void**)&gq, g_q);
    cudaGetSymbolAddress((void**)&gk, g_k);
    cudaGetSymbolAddress((void**)&gv, g_v);
    cudaGetSymbolAddress((void**)&ga, g_attn);

    cudaFuncSetAttribute(fused_proj,
                         cudaFuncAttributeMaxDynamicSharedMemorySize, FP_SMEM);
    cudaFuncSetAttribute(attn_mma,
                         cudaFuncAttributeMaxDynamicSharedMemorySize, AT_SMEM);

    // one-time-per-call weight preconversion (fp16, swizzled chunk layout)
    wcvt<<<48, 256>>>(Wq, Wkv, Wscale, Wshift, Wout);

    // Fused scale/shift/q/k/v projections with FiLM (512 threads, fp16 out)
    fused_proj<<<MROWS / 64, 512, FP_SMEM>>>(x, ctx, gq, gk, gv);

    // attention: 1024 batches x 8 heads, tensor-core, fp16 in/out
    attn_mma<<<8192, 128, AT_SMEM>>>(gq, gk, gv, ga);

    // output projection straight into d_out
    gemm_h16<<<dim3(2, 1024), 256>>>(ga, out);
}